// round 5
// baseline (speedup 1.0000x reference)
#include <cuda_runtime.h>
#include <cuda_bf16.h>
#include <cstdint>

// Problem constants
#define Bsz 4
#define Sq  2048
#define Hd  1024
#define NH  16
#define HD  64
#define BH  (Bsz*NH)          // 64
#define M1  (Bsz*Sq)          // 8192
#define QKV_STRIDE ((size_t)BH*Sq*HD) // 8388608 elems per Q/K/V

// Scratch (__device__ globals; g_qkv holds tf32 bit patterns)
__device__ uint32_t g_qkv[3ull * QKV_STRIDE];   // Q(pre-scaled),K,V each [BH,S,HD]
__device__ float    g_ctx[(size_t)M1 * Hd];     // [B, S, H]

// ---------------------------------------------------------------------------
// Helpers
// ---------------------------------------------------------------------------
__device__ __forceinline__ uint32_t f2tf32(float f) {
    uint32_t u;
    asm("cvt.rna.tf32.f32 %0, %1;" : "=r"(u) : "f"(f));
    return u;
}
__device__ __forceinline__ void cp_async16(void* smem_dst, const void* gmem_src) {
    uint32_t s = (uint32_t)__cvta_generic_to_shared(smem_dst);
    asm volatile("cp.async.ca.shared.global [%0], [%1], 16;\n" :: "r"(s), "l"(gmem_src));
}
#define CP_COMMIT() asm volatile("cp.async.commit_group;\n")
#define CP_WAIT(n)  asm volatile("cp.async.wait_group %0;\n" :: "n"(n))

#define MMA_TF32(acc, a, b0, b1)                                               \
    asm volatile(                                                              \
        "mma.sync.aligned.m16n8k8.row.col.f32.tf32.tf32.f32 "                  \
        "{%0,%1,%2,%3}, {%4,%5,%6,%7}, {%8,%9}, {%0,%1,%2,%3};\n"              \
        : "+f"((acc)[0]), "+f"((acc)[1]), "+f"((acc)[2]), "+f"((acc)[3])       \
        : "r"((a)[0]), "r"((a)[1]), "r"((a)[2]), "r"((a)[3]),                  \
          "r"(b0), "r"(b1))

// ---------------------------------------------------------------------------
// TF32 tensor-core GEMM: C = A[M,K] @ B[K,N] + bias. 128x128x16 tiles,
// 256 thr, warp tile 64x32. cvt at STS time -> inner loop pure LDS+MMA.
// MODE 0: fp32 row-major C. MODE 1: tf32-bits scatter into g_qkv (Q *= 1/8).
// ---------------------------------------------------------------------------
#define BKP 20
#define BNP 136

template<int MODE>
__global__ __launch_bounds__(256)
void tf32_gemm(const float* __restrict__ A, const float* __restrict__ Bm,
               const float* __restrict__ bias, float* __restrict__ C,
               int M, int N, int K)
{
    __shared__ uint32_t As[2][128 * BKP];
    __shared__ uint32_t Bs[2][16 * BNP];

    const int tid  = threadIdx.x;
    const int lane = tid & 31;
    const int warp = tid >> 5;
    const int wm   = (warp >> 2) * 64;
    const int wn   = (warp & 3) * 32;
    const int brow = blockIdx.y * 128;
    const int bcol = blockIdx.x * 128;
    const int lg = lane >> 2;
    const int lt = lane & 3;

    // loader indices (2 chunks of A, 2 of B per thread)
    const int arow0 = tid >> 2,        aseg0 = (tid & 3) * 4;
    const int arow1 = (tid + 256) >> 2, aseg1 = aseg0;
    const int brw0  = tid >> 5,        bseg0 = (tid & 31) * 4;
    const int brw1  = (tid + 256) >> 5, bseg1 = bseg0;

    float4 ar0, ar1, br0, br1;
    auto ldg_tile = [&](int k0) {
        ar0 = *(const float4*)(A + (size_t)(brow + arow0) * K + k0 + aseg0);
        ar1 = *(const float4*)(A + (size_t)(brow + arow1) * K + k0 + aseg1);
        br0 = *(const float4*)(Bm + (size_t)(k0 + brw0) * N + bcol + bseg0);
        br1 = *(const float4*)(Bm + (size_t)(k0 + brw1) * N + bcol + bseg1);
    };
    auto sts_tile = [&](int buf) {
        uint4 u;
        u.x = f2tf32(ar0.x); u.y = f2tf32(ar0.y); u.z = f2tf32(ar0.z); u.w = f2tf32(ar0.w);
        *(uint4*)&As[buf][arow0 * BKP + aseg0] = u;
        u.x = f2tf32(ar1.x); u.y = f2tf32(ar1.y); u.z = f2tf32(ar1.z); u.w = f2tf32(ar1.w);
        *(uint4*)&As[buf][arow1 * BKP + aseg1] = u;
        u.x = f2tf32(br0.x); u.y = f2tf32(br0.y); u.z = f2tf32(br0.z); u.w = f2tf32(br0.w);
        *(uint4*)&Bs[buf][brw0 * BNP + bseg0] = u;
        u.x = f2tf32(br1.x); u.y = f2tf32(br1.y); u.z = f2tf32(br1.z); u.w = f2tf32(br1.w);
        *(uint4*)&Bs[buf][brw1 * BNP + bseg1] = u;
    };

    float acc[4][4][4];
#pragma unroll
    for (int mi = 0; mi < 4; mi++)
#pragma unroll
        for (int ni = 0; ni < 4; ni++)
#pragma unroll
            for (int r = 0; r < 4; r++) acc[mi][ni][r] = 0.f;

    ldg_tile(0);
    sts_tile(0);
    __syncthreads();

    const int NIT = K / 16;
    int buf = 0;
    for (int it = 0; it < NIT; ++it) {
        if (it + 1 < NIT) ldg_tile((it + 1) * 16);   // overlap with compute

#pragma unroll
        for (int ks = 0; ks < 2; ++ks) {
            const int k8 = ks * 8;
            uint32_t af[4][4], bf[4][2];
#pragma unroll
            for (int mi = 0; mi < 4; mi++) {
                int row = wm + mi * 16 + lg;
                af[mi][0] = As[buf][row * BKP + k8 + lt];
                af[mi][1] = As[buf][(row + 8) * BKP + k8 + lt];
                af[mi][2] = As[buf][row * BKP + k8 + lt + 4];
                af[mi][3] = As[buf][(row + 8) * BKP + k8 + lt + 4];
            }
#pragma unroll
            for (int ni = 0; ni < 4; ni++) {
                int col = wn + ni * 8 + lg;
                bf[ni][0] = Bs[buf][(k8 + lt) * BNP + col];
                bf[ni][1] = Bs[buf][(k8 + 4 + lt) * BNP + col];
            }
#pragma unroll
            for (int mi = 0; mi < 4; mi++)
#pragma unroll
                for (int ni = 0; ni < 4; ni++)
                    MMA_TF32(acc[mi][ni], af[mi], bf[ni][0], bf[ni][1]);
        }
        __syncthreads();
        if (it + 1 < NIT) {
            sts_tile(buf ^ 1);
            __syncthreads();
        }
        buf ^= 1;
    }

    // epilogue
#pragma unroll
    for (int mi = 0; mi < 4; mi++) {
#pragma unroll
        for (int ni = 0; ni < 4; ni++) {
            int gr = brow + wm + mi * 16 + lg;
            int gc = bcol + wn + ni * 8 + lt * 2;
            float bx = bias[gc], by = bias[gc + 1];
            float2 v0 = make_float2(acc[mi][ni][0] + bx, acc[mi][ni][1] + by);
            float2 v1 = make_float2(acc[mi][ni][2] + bx, acc[mi][ni][3] + by);
            if (MODE == 0) {
                *(float2*)&C[(size_t)gr * N + gc]       = v0;
                *(float2*)&C[(size_t)(gr + 8) * N + gc] = v1;
            } else {
                int which = gc >> 10;
                int hh    = (gc >> 6) & 15;
                int d     = gc & 63;
                float scale = (which == 0) ? 0.125f : 1.0f;  // fold 1/sqrt(HD) into Q
#pragma unroll
                for (int rr = 0; rr < 2; rr++) {
                    int row = gr + rr * 8;
                    int b   = row >> 11;
                    int s   = row & 2047;
                    float2 v = rr ? v1 : v0;
                    uint2 u;
                    u.x = f2tf32(v.x * scale);
                    u.y = f2tf32(v.y * scale);
                    size_t idx = (size_t)which * QKV_STRIDE
                               + (((size_t)(b * NH + hh) * Sq + s) * HD) + d;
                    *(uint2*)&g_qkv[idx] = u;
                }
            }
        }
    }
}

// ---------------------------------------------------------------------------
// TF32 tensor-core causal flash attention.
// BM=128 (8 warps x 16 rows), BN=64, HD=64. Q frags in regs, K/V cp.async
// double-buffered, m/l in regs, P via warp-private smem region.
// Smem pad 72 (72%32==8): all fragment access patterns conflict-free.
// ---------------------------------------------------------------------------
#define AT_PAD 72
#define AT_KV_SZ (64 * AT_PAD)                       // 4608 words per K or V buf
#define AT_SMEM_WORDS (4 * AT_KV_SZ + 128 * AT_PAD)  // 27648 words = 110592 B

__global__ __launch_bounds__(256)
void attn_tc(const uint32_t* __restrict__ gQ, const uint32_t* __restrict__ gK,
             const uint32_t* __restrict__ gV)
{
    extern __shared__ uint32_t sm[];
    uint32_t* KsBuf[2] = { sm,             sm + 2 * AT_KV_SZ };
    uint32_t* VsBuf[2] = { sm + AT_KV_SZ,  sm + 3 * AT_KV_SZ };
    uint32_t* Ps       = sm + 4 * AT_KV_SZ;          // [128][AT_PAD]

    const int tid  = threadIdx.x;
    const int lane = tid & 31;
    const int warp = tid >> 5;
    const int lg = lane >> 2;
    const int lt = lane & 3;
    const int qt = 15 - blockIdx.x;     // heavy tiles first
    const int bh = blockIdx.y;
    const int q0 = qt * 128;
    const int wm = warp * 16;

    const uint32_t* q_ptr = gQ + ((size_t)bh * Sq + q0) * HD;

    // prefetch Q (128x64) into Ps
#pragma unroll
    for (int r = 0; r < 8; r++) {
        int f = tid + r * 256;
        int row = f >> 4, seg = f & 15;
        cp_async16(&Ps[row * AT_PAD + seg * 4], q_ptr + (size_t)row * HD + seg * 4);
    }
    CP_COMMIT();

    auto load_kv = [&](int kt, int b) {
        const uint32_t* k_ptr = gK + ((size_t)bh * Sq + kt * 64) * HD;
        const uint32_t* v_ptr = gV + ((size_t)bh * Sq + kt * 64) * HD;
#pragma unroll
        for (int r = 0; r < 4; r++) {
            int f = tid + r * 256;
            int row = f >> 4, seg = f & 15;
            cp_async16(&KsBuf[b][row * AT_PAD + seg * 4], k_ptr + (size_t)row * HD + seg * 4);
            cp_async16(&VsBuf[b][row * AT_PAD + seg * 4], v_ptr + (size_t)row * HD + seg * 4);
        }
    };
    load_kv(0, 0);
    CP_COMMIT();

    CP_WAIT(1);           // Q landed
    __syncthreads();

    // Q fragments (warp-private rows of Ps; no further sync needed)
    uint32_t qf[8][4];
#pragma unroll
    for (int k = 0; k < 8; k++) {
        qf[k][0] = Ps[(wm + lg) * AT_PAD + k * 8 + lt];
        qf[k][1] = Ps[(wm + lg + 8) * AT_PAD + k * 8 + lt];
        qf[k][2] = Ps[(wm + lg) * AT_PAD + k * 8 + lt + 4];
        qf[k][3] = Ps[(wm + lg + 8) * AT_PAD + k * 8 + lt + 4];
    }

    float m_lo = -1e30f, m_hi = -1e30f, l_lo = 0.f, l_hi = 0.f;
    float o[8][4];
#pragma unroll
    for (int ni = 0; ni < 8; ni++)
#pragma unroll
        for (int c = 0; c < 4; c++) o[ni][c] = 0.f;

    const int row_lo = q0 + wm + lg;
    const int row_hi = row_lo + 8;
    const int nkt = 2 * qt + 2;

    for (int kt = 0; kt < nkt; kt++) {
        const int p = kt & 1;
        CP_WAIT(0);
        __syncthreads();                          // tile ready; prev tile reads done
        if (kt + 1 < nkt) { load_kv(kt + 1, p ^ 1); CP_COMMIT(); }

        const uint32_t* Ks = KsBuf[p];
        const uint32_t* Vs = VsBuf[p];

        // S = Q @ K^T  (scale pre-folded into Q)
        float s[8][4];
#pragma unroll
        for (int ni = 0; ni < 8; ni++)
#pragma unroll
            for (int c = 0; c < 4; c++) s[ni][c] = 0.f;

#pragma unroll
        for (int k = 0; k < 8; k++) {
#pragma unroll
            for (int ni = 0; ni < 8; ni++) {
                uint32_t b0 = Ks[(ni * 8 + lg) * AT_PAD + k * 8 + lt];
                uint32_t b1 = Ks[(ni * 8 + lg) * AT_PAD + k * 8 + lt + 4];
                MMA_TF32(s[ni], qf[k], b0, b1);
            }
        }

        // causal mask (only near the diagonal)
        if (kt >= 2 * qt) {
            const int colb = kt * 64;
#pragma unroll
            for (int ni = 0; ni < 8; ni++) {
                int c0 = colb + ni * 8 + lt * 2;
                if (c0 > row_lo)     s[ni][0] = -1e30f;
                if (c0 + 1 > row_lo) s[ni][1] = -1e30f;
                if (c0 > row_hi)     s[ni][2] = -1e30f;
                if (c0 + 1 > row_hi) s[ni][3] = -1e30f;
            }
        }

        // online softmax (row stats in regs, reduce over the 4-lane quad)
        float rx_lo = -1e30f, rx_hi = -1e30f;
#pragma unroll
        for (int ni = 0; ni < 8; ni++) {
            rx_lo = fmaxf(rx_lo, fmaxf(s[ni][0], s[ni][1]));
            rx_hi = fmaxf(rx_hi, fmaxf(s[ni][2], s[ni][3]));
        }
        rx_lo = fmaxf(rx_lo, __shfl_xor_sync(0xffffffffu, rx_lo, 1));
        rx_lo = fmaxf(rx_lo, __shfl_xor_sync(0xffffffffu, rx_lo, 2));
        rx_hi = fmaxf(rx_hi, __shfl_xor_sync(0xffffffffu, rx_hi, 1));
        rx_hi = fmaxf(rx_hi, __shfl_xor_sync(0xffffffffu, rx_hi, 2));

        float mn_lo = fmaxf(m_lo, rx_lo);
        float mn_hi = fmaxf(m_hi, rx_hi);
        float al_lo = __expf(m_lo - mn_lo);
        float al_hi = __expf(m_hi - mn_hi);
        m_lo = mn_lo; m_hi = mn_hi;

        float rs_lo = 0.f, rs_hi = 0.f;
#pragma unroll
        for (int ni = 0; ni < 8; ni++) {
            s[ni][0] = __expf(s[ni][0] - mn_lo);
            s[ni][1] = __expf(s[ni][1] - mn_lo);
            s[ni][2] = __expf(s[ni][2] - mn_hi);
            s[ni][3] = __expf(s[ni][3] - mn_hi);
            rs_lo += s[ni][0] + s[ni][1];
            rs_hi += s[ni][2] + s[ni][3];
        }
        rs_lo += __shfl_xor_sync(0xffffffffu, rs_lo, 1);
        rs_lo += __shfl_xor_sync(0xffffffffu, rs_lo, 2);
        rs_hi += __shfl_xor_sync(0xffffffffu, rs_hi, 1);
        rs_hi += __shfl_xor_sync(0xffffffffu, rs_hi, 2);
        l_lo = l_lo * al_lo + rs_lo;
        l_hi = l_hi * al_hi + rs_hi;

#pragma unroll
        for (int ni = 0; ni < 8; ni++) {
            o[ni][0] *= al_lo; o[ni][1] *= al_lo;
            o[ni][2] *= al_hi; o[ni][3] *= al_hi;
        }

        // store P (tf32) into warp-private Ps rows
#pragma unroll
        for (int ni = 0; ni < 8; ni++) {
            uint2 u0 = make_uint2(f2tf32(s[ni][0]), f2tf32(s[ni][1]));
            uint2 u1 = make_uint2(f2tf32(s[ni][2]), f2tf32(s[ni][3]));
            *(uint2*)&Ps[(wm + lg) * AT_PAD + ni * 8 + lt * 2]     = u0;
            *(uint2*)&Ps[(wm + lg + 8) * AT_PAD + ni * 8 + lt * 2] = u1;
        }
        __syncwarp();

        // O += P @ V
#pragma unroll
        for (int k = 0; k < 8; k++) {
            uint32_t pf[4];
            pf[0] = Ps[(wm + lg) * AT_PAD + k * 8 + lt];
            pf[1] = Ps[(wm + lg + 8) * AT_PAD + k * 8 + lt];
            pf[2] = Ps[(wm + lg) * AT_PAD + k * 8 + lt + 4];
            pf[3] = Ps[(wm + lg + 8) * AT_PAD + k * 8 + lt + 4];
#pragma unroll
            for (int ni = 0; ni < 8; ni++) {
                uint32_t b0 = Vs[(k * 8 + lt) * AT_PAD + ni * 8 + lg];
                uint32_t b1 = Vs[(k * 8 + lt + 4) * AT_PAD + ni * 8 + lg];
                MMA_TF32(o[ni], pf, b0, b1);
            }
        }
        __syncwarp();   // Ps reads done before next iteration's P store
    }

    // epilogue: normalize, write ctx [B,S,H]
    const int b = bh >> 4;
    const int h = bh & 15;
    const float inv_lo = 1.f / l_lo;
    const float inv_hi = 1.f / l_hi;
#pragma unroll
    for (int ni = 0; ni < 8; ni++) {
        int d = ni * 8 + lt * 2;
        float2 v0 = make_float2(o[ni][0] * inv_lo, o[ni][1] * inv_lo);
        float2 v1 = make_float2(o[ni][2] * inv_hi, o[ni][3] * inv_hi);
        size_t i0 = (((size_t)b * Sq + row_lo) << 10) + h * HD + d;
        size_t i1 = (((size_t)b * Sq + row_hi) << 10) + h * HD + d;
        *(float2*)&g_ctx[i0] = v0;
        *(float2*)&g_ctx[i1] = v1;
    }
}

// ---------------------------------------------------------------------------
// Launch
// ---------------------------------------------------------------------------
extern "C" void kernel_launch(void* const* d_in, const int* in_sizes, int n_in,
                              void* d_out, int out_size)
{
    const float* X       = (const float*)d_in[0];
    const float* W_qkv   = (const float*)d_in[2];
    const float* b_qkv   = (const float*)d_in[3];
    const float* W_dense = (const float*)d_in[4];
    const float* b_dense = (const float*)d_in[5];
    float* out = (float*)d_out;

    (void)in_sizes; (void)n_in; (void)out_size;

    cudaFuncSetAttribute(attn_tc,
                         cudaFuncAttributeMaxDynamicSharedMemorySize,
                         AT_SMEM_WORDS * 4);

    // 1. QKV projection -> tf32 bits in head layout (Q pre-scaled by 1/8)
    tf32_gemm<1><<<dim3(3 * Hd / 128, M1 / 128), 256>>>(
        X, W_qkv, b_qkv, nullptr, M1, 3 * Hd, Hd);

    // 2. tensor-core causal flash attention
    {
        uint32_t* base;
        cudaGetSymbolAddress((void**)&base, g_qkv);
        attn_tc<<<dim3(16, BH), 256, AT_SMEM_WORDS * 4>>>(
            base, base + QKV_STRIDE, base + 2 * QKV_STRIDE);
    }

    // 3. output projection
    {
        float* ctx;
        cudaGetSymbolAddress((void**)&ctx, g_ctx);
        tf32_gemm<0><<<dim3(Hd / 128, M1 / 128), 256>>>(
            ctx, W_dense, b_dense, out, M1, Hd, Hd);
    }
}

// round 7
// speedup vs baseline: 1.3602x; 1.3602x over previous
#include <cuda_runtime.h>
#include <cuda_fp16.h>
#include <cstdint>

// Problem constants
#define Bsz 4
#define Sq  2048
#define Hd  1024
#define NH  16
#define HD  64
#define BH  (Bsz*NH)          // 64
#define M1  (Bsz*Sq)          // 8192
#define QKV_STRIDE ((size_t)BH*Sq*HD) // 8388608 halves per tensor

// Scratch (__device__ globals)
__device__ __half g_q  [QKV_STRIDE];            // [BH][S][HD], pre-scaled 1/8
__device__ __half g_k  [QKV_STRIDE];            // [BH][S][HD]
__device__ __half g_vT [QKV_STRIDE];            // [BH][HD][S]  (transposed!)
__device__ __half g_ctx[(size_t)M1 * Hd];       // [B][S][H]
__device__ __half g_Xh [(size_t)M1 * Hd];       // X as half
__device__ __half g_Wqt[(size_t)3 * Hd * Hd];   // W_qkv^T  [3072][1024]
__device__ __half g_Wdt[(size_t)Hd * Hd];       // W_dense^T [1024][1024]

// ---------------------------------------------------------------------------
// Helpers
// ---------------------------------------------------------------------------
__device__ __forceinline__ uint32_t pack_h2(float a, float b) {
    __half2 h = __floats2half2_rn(a, b);
    return *(uint32_t*)&h;
}
__device__ __forceinline__ void cp_async16(void* smem_dst, const void* gmem_src) {
    uint32_t s = (uint32_t)__cvta_generic_to_shared(smem_dst);
    asm volatile("cp.async.ca.shared.global [%0], [%1], 16;\n" :: "r"(s), "l"(gmem_src));
}
#define CP_COMMIT() asm volatile("cp.async.commit_group;\n")
#define CP_WAIT(n)  asm volatile("cp.async.wait_group %0;\n" :: "n"(n))

// fp16 mma, fp32 accum. A row-major (4 regs), B col-major (2 regs).
#define MMA_F16(acc, a, b0, b1)                                                \
    asm volatile(                                                              \
        "mma.sync.aligned.m16n8k16.row.col.f32.f16.f16.f32 "                   \
        "{%0,%1,%2,%3}, {%4,%5,%6,%7}, {%8,%9}, {%0,%1,%2,%3};\n"              \
        : "+f"((acc)[0]), "+f"((acc)[1]), "+f"((acc)[2]), "+f"((acc)[3])       \
        : "r"((a)[0]), "r"((a)[1]), "r"((a)[2]), "r"((a)[3]),                  \
          "r"(b0), "r"(b1))

// ---------------------------------------------------------------------------
// Prep: X fp32 -> half;  W fp32 [R][C] -> W^T half [C][R]
// ---------------------------------------------------------------------------
__global__ void conv_h(const float4* __restrict__ src, uint2* __restrict__ dst, int n4) {
    int i = blockIdx.x * blockDim.x + threadIdx.x;
    if (i < n4) {
        float4 v = src[i];
        dst[i] = make_uint2(pack_h2(v.x, v.y), pack_h2(v.z, v.w));
    }
}
__global__ void transp_h(const float* __restrict__ src, __half* __restrict__ dst,
                         int R, int C) {
    __shared__ __half t[32][33];
    int c0 = blockIdx.x * 32, r0 = blockIdx.y * 32;
    int tx = threadIdx.x, ty = threadIdx.y;   // 32 x 8
#pragma unroll
    for (int i = 0; i < 32; i += 8)
        t[ty + i][tx] = __float2half_rn(src[(size_t)(r0 + ty + i) * C + c0 + tx]);
    __syncthreads();
#pragma unroll
    for (int i = 0; i < 32; i += 8)
        dst[(size_t)(c0 + ty + i) * R + r0 + tx] = t[tx][ty + i];
}

// ---------------------------------------------------------------------------
// FP16 tensor-core GEMM: C[M,N] = A[M,1024] @ Bw^T + bias
// A half row-major [.,1024]; Bw half [N][1024] (K-major).
// 128x128x32 tiles, 256 thr (8 warps, 2x4), warp tile 64x32, double buffer.
// Smem row stride 40 halves (20 words): all frag LDS conflict-free.
// MODE 0: fp32 row-major C.  MODE 1: scatter to g_q(1/8)/g_k/g_vT.
// ---------------------------------------------------------------------------
template<int MODE>
__global__ __launch_bounds__(256)
void gemm_h(const __half* __restrict__ A, const __half* __restrict__ Bw,
            const float* __restrict__ bias, float* __restrict__ C, int N)
{
    __shared__ __half As[2][128 * 40];
    __shared__ __half Bs[2][128 * 40];

    const int tid  = threadIdx.x;
    const int lane = tid & 31;
    const int warp = tid >> 5;
    const int wm   = (warp >> 2) * 64;
    const int wn   = (warp & 3) * 32;
    const int brow = blockIdx.y * 128;
    const int bcol = blockIdx.x * 128;
    const int lg = lane >> 2;
    const int lt = lane & 3;

    // loader: row = tid&127, two 16B segs; whole warp same seg -> all 32 banks
    const int lrow = tid & 127;
    const int lsg  = (tid >> 7) * 2;

    auto fill = [&](int k0, int buf) {
        const __half* Ag = A  + (size_t)(brow + lrow) * 1024 + k0;
        const __half* Bg = Bw + (size_t)(bcol + lrow) * 1024 + k0;
#pragma unroll
        for (int i = 0; i < 2; i++) {
            cp_async16(&As[buf][lrow * 40 + (lsg + i) * 8], Ag + (lsg + i) * 8);
            cp_async16(&Bs[buf][lrow * 40 + (lsg + i) * 8], Bg + (lsg + i) * 8);
        }
        CP_COMMIT();
    };

    float acc[4][4][4];
#pragma unroll
    for (int mi = 0; mi < 4; mi++)
#pragma unroll
        for (int ni = 0; ni < 4; ni++)
#pragma unroll
            for (int r = 0; r < 4; r++) acc[mi][ni][r] = 0.f;

    fill(0, 0);
    int buf = 0;
    const int NIT = 1024 / 32;
    for (int it = 0; it < NIT; ++it) {
        if (it + 1 < NIT) { fill((it + 1) * 32, buf ^ 1); CP_WAIT(1); }
        else CP_WAIT(0);
        __syncthreads();

        const uint32_t* Aw = (const uint32_t*)As[buf];
        const uint32_t* Bv = (const uint32_t*)Bs[buf];
#pragma unroll
        for (int ks = 0; ks < 2; ++ks) {
            uint32_t af[4][4], bf[4][2];
#pragma unroll
            for (int mi = 0; mi < 4; mi++) {
                int row = wm + mi * 16 + lg;
                af[mi][0] = Aw[row * 20 + ks * 8 + lt];
                af[mi][1] = Aw[(row + 8) * 20 + ks * 8 + lt];
                af[mi][2] = Aw[row * 20 + ks * 8 + lt + 4];
                af[mi][3] = Aw[(row + 8) * 20 + ks * 8 + lt + 4];
            }
#pragma unroll
            for (int ni = 0; ni < 4; ni++) {
                int n = wn + ni * 8 + lg;
                bf[ni][0] = Bv[n * 20 + ks * 8 + lt];
                bf[ni][1] = Bv[n * 20 + ks * 8 + lt + 4];
            }
#pragma unroll
            for (int mi = 0; mi < 4; mi++)
#pragma unroll
                for (int ni = 0; ni < 4; ni++)
                    MMA_F16(acc[mi][ni], af[mi], bf[ni][0], bf[ni][1]);
        }
        __syncthreads();
        buf ^= 1;
    }

    // epilogue
#pragma unroll
    for (int mi = 0; mi < 4; mi++) {
#pragma unroll
        for (int ni = 0; ni < 4; ni++) {
            int gr = brow + wm + mi * 16 + lg;
            int gc = bcol + wn + ni * 8 + lt * 2;
            float bx = bias[gc], by = bias[gc + 1];
            float2 v0 = make_float2(acc[mi][ni][0] + bx, acc[mi][ni][1] + by);
            float2 v1 = make_float2(acc[mi][ni][2] + bx, acc[mi][ni][3] + by);
            if (MODE == 0) {
                *(float2*)&C[(size_t)gr * N + gc]       = v0;
                *(float2*)&C[(size_t)(gr + 8) * N + gc] = v1;
            } else {
                int which = gc >> 10;
                int hh    = (gc >> 6) & 15;
                int d     = gc & 63;
#pragma unroll
                for (int rr = 0; rr < 2; rr++) {
                    int row = gr + rr * 8;
                    int b   = row >> 11;
                    int s   = row & 2047;
                    int bh  = b * NH + hh;
                    float2 v = rr ? v1 : v0;
                    if (which == 0) {
                        *(uint32_t*)&g_q[((size_t)bh * Sq + s) * HD + d] =
                            pack_h2(v.x * 0.125f, v.y * 0.125f);
                    } else if (which == 1) {
                        *(uint32_t*)&g_k[((size_t)bh * Sq + s) * HD + d] =
                            pack_h2(v.x, v.y);
                    } else {
                        g_vT[((size_t)bh * HD + d)     * Sq + s] = __float2half_rn(v.x);
                        g_vT[((size_t)bh * HD + d + 1) * Sq + s] = __float2half_rn(v.y);
                    }
                }
            }
        }
    }
}

// ---------------------------------------------------------------------------
// FP16 tensor-core causal flash attention.
// BM=128 (8 warps x 16 rows), BN=64, HD=64. Q frags in regs; Ps aliases Qs.
// Smem rows 64 halves + 8 pad = 36 words: all frag patterns conflict-free.
// ---------------------------------------------------------------------------
#define AQ_W (128 * 36)              // Qs / Ps (aliased)
#define AK_W (64 * 36)               // each K or VT buffer
#define AT_WORDS (AQ_W + 4 * AK_W)   // 13824 words = 55296 B

__global__ __launch_bounds__(256)
void attn_h()
{
    extern __shared__ uint32_t sm[];
    uint32_t* Qs  = sm;                          // [128][36] words (also Ps)
    uint32_t* Kb[2]  = { sm + AQ_W,            sm + AQ_W + 2 * AK_W };
    uint32_t* Vb[2]  = { sm + AQ_W + AK_W,     sm + AQ_W + 3 * AK_W };

    const int tid  = threadIdx.x;
    const int lane = tid & 31;
    const int warp = tid >> 5;
    const int lg = lane >> 2;
    const int lt = lane & 3;
    const int qt = 15 - blockIdx.x;
    const int bh = blockIdx.y;
    const int q0 = qt * 128;
    const int wm = warp * 16;

    // Q load: 1024 x 16B chunks
    const __half* q_ptr = g_q + ((size_t)bh * Sq + q0) * HD;
#pragma unroll
    for (int i = 0; i < 4; i++) {
        int id = tid + i * 256;
        int row = id >> 3, seg = id & 7;
        cp_async16((char*)&Qs[row * 36] + seg * 16, q_ptr + (size_t)row * HD + seg * 8);
    }
    CP_COMMIT();

    auto load_kv = [&](int kt, int b) {
        const __half* k_ptr = g_k  + ((size_t)bh * Sq + kt * 64) * HD;
        const __half* v_ptr = g_vT + (size_t)bh * HD * Sq + kt * 64;
#pragma unroll
        for (int i = 0; i < 2; i++) {
            int id = tid + i * 256;
            int row = id >> 3, seg = id & 7;
            cp_async16((char*)&Kb[b][row * 36] + seg * 16, k_ptr + (size_t)row * HD + seg * 8);
            cp_async16((char*)&Vb[b][row * 36] + seg * 16, v_ptr + (size_t)row * Sq + seg * 8);
        }
        CP_COMMIT();
    };
    load_kv(0, 0);

    CP_WAIT(1);          // Q landed
    __syncthreads();

    // Q fragments (warp-private rows): qf[ks][4]
    uint32_t qf[4][4];
#pragma unroll
    for (int ks = 0; ks < 4; ks++) {
        qf[ks][0] = Qs[(wm + lg) * 36 + ks * 8 + lt];
        qf[ks][1] = Qs[(wm + lg + 8) * 36 + ks * 8 + lt];
        qf[ks][2] = Qs[(wm + lg) * 36 + ks * 8 + lt + 4];
        qf[ks][3] = Qs[(wm + lg + 8) * 36 + ks * 8 + lt + 4];
    }
    uint32_t* Ps = Qs;   // alias: Q no longer needed from smem

    float m_lo = -1e30f, m_hi = -1e30f, l_lo = 0.f, l_hi = 0.f;
    float o[8][4];
#pragma unroll
    for (int ni = 0; ni < 8; ni++)
#pragma unroll
        for (int c = 0; c < 4; c++) o[ni][c] = 0.f;

    const int row_lo = q0 + wm + lg;
    const int row_hi = row_lo + 8;
    const int nkt = 2 * qt + 2;

    for (int kt = 0; kt < nkt; kt++) {
        const int p = kt & 1;
        CP_WAIT(0);
        __syncthreads();
        if (kt + 1 < nkt) load_kv(kt + 1, p ^ 1);

        const uint32_t* Ks = Kb[p];
        const uint32_t* Vs = Vb[p];

        // S = Q @ K^T (scale folded into Q)
        float s[8][4];
#pragma unroll
        for (int ni = 0; ni < 8; ni++)
#pragma unroll
            for (int c = 0; c < 4; c++) s[ni][c] = 0.f;

#pragma unroll
        for (int ks = 0; ks < 4; ks++)
#pragma unroll
            for (int ni = 0; ni < 8; ni++) {
                uint32_t b0 = Ks[(ni * 8 + lg) * 36 + ks * 8 + lt];
                uint32_t b1 = Ks[(ni * 8 + lg) * 36 + ks * 8 + lt + 4];
                MMA_F16(s[ni], qf[ks], b0, b1);
            }

        if (kt >= 2 * qt) {
            const int colb = kt * 64;
#pragma unroll
            for (int ni = 0; ni < 8; ni++) {
                int c0 = colb + ni * 8 + lt * 2;
                if (c0 > row_lo)     s[ni][0] = -1e30f;
                if (c0 + 1 > row_lo) s[ni][1] = -1e30f;
                if (c0 > row_hi)     s[ni][2] = -1e30f;
                if (c0 + 1 > row_hi) s[ni][3] = -1e30f;
            }
        }

        // online softmax (stats in regs, quad reduce)
        float rx_lo = -1e30f, rx_hi = -1e30f;
#pragma unroll
        for (int ni = 0; ni < 8; ni++) {
            rx_lo = fmaxf(rx_lo, fmaxf(s[ni][0], s[ni][1]));
            rx_hi = fmaxf(rx_hi, fmaxf(s[ni][2], s[ni][3]));
        }
        rx_lo = fmaxf(rx_lo, __shfl_xor_sync(0xffffffffu, rx_lo, 1));
        rx_lo = fmaxf(rx_lo, __shfl_xor_sync(0xffffffffu, rx_lo, 2));
        rx_hi = fmaxf(rx_hi, __shfl_xor_sync(0xffffffffu, rx_hi, 1));
        rx_hi = fmaxf(rx_hi, __shfl_xor_sync(0xffffffffu, rx_hi, 2));

        float mn_lo = fmaxf(m_lo, rx_lo);
        float mn_hi = fmaxf(m_hi, rx_hi);
        float al_lo = __expf(m_lo - mn_lo);
        float al_hi = __expf(m_hi - mn_hi);
        m_lo = mn_lo; m_hi = mn_hi;

        float rs_lo = 0.f, rs_hi = 0.f;
#pragma unroll
        for (int ni = 0; ni < 8; ni++) {
            s[ni][0] = __expf(s[ni][0] - mn_lo);
            s[ni][1] = __expf(s[ni][1] - mn_lo);
            s[ni][2] = __expf(s[ni][2] - mn_hi);
            s[ni][3] = __expf(s[ni][3] - mn_hi);
            rs_lo += s[ni][0] + s[ni][1];
            rs_hi += s[ni][2] + s[ni][3];
        }
        rs_lo += __shfl_xor_sync(0xffffffffu, rs_lo, 1);
        rs_lo += __shfl_xor_sync(0xffffffffu, rs_lo, 2);
        rs_hi += __shfl_xor_sync(0xffffffffu, rs_hi, 1);
        rs_hi += __shfl_xor_sync(0xffffffffu, rs_hi, 2);
        l_lo = l_lo * al_lo + rs_lo;
        l_hi = l_hi * al_hi + rs_hi;

#pragma unroll
        for (int ni = 0; ni < 8; ni++) {
            o[ni][0] *= al_lo; o[ni][1] *= al_lo;
            o[ni][2] *= al_hi; o[ni][3] *= al_hi;
        }

        // P (half2) into warp-private Ps rows
#pragma unroll
        for (int ni = 0; ni < 8; ni++) {
            Ps[(wm + lg) * 36 + ni * 4 + lt]     = pack_h2(s[ni][0], s[ni][1]);
            Ps[(wm + lg + 8) * 36 + ni * 4 + lt] = pack_h2(s[ni][2], s[ni][3]);
        }
        __syncwarp();

        // O += P @ V  (V^T tile: rows = d, cols = keys)
#pragma unroll
        for (int ks = 0; ks < 4; ks++) {
            uint32_t pf[4];
            pf[0] = Ps[(wm + lg) * 36 + ks * 8 + lt];
            pf[1] = Ps[(wm + lg + 8) * 36 + ks * 8 + lt];
            pf[2] = Ps[(wm + lg) * 36 + ks * 8 + lt + 4];
            pf[3] = Ps[(wm + lg + 8) * 36 + ks * 8 + lt + 4];
#pragma unroll
            for (int ni = 0; ni < 8; ni++) {
                uint32_t b0 = Vs[(ni * 8 + lg) * 36 + ks * 8 + lt];
                uint32_t b1 = Vs[(ni * 8 + lg) * 36 + ks * 8 + lt + 4];
                MMA_F16(o[ni], pf, b0, b1);
            }
        }
        __syncwarp();
    }

    // epilogue: normalize, write ctx as half
    const int b = bh >> 4;
    const int h = bh & 15;
    const float inv_lo = 1.f / l_lo;
    const float inv_hi = 1.f / l_hi;
#pragma unroll
    for (int ni = 0; ni < 8; ni++) {
        int d = ni * 8 + lt * 2;
        size_t i0 = (((size_t)b * Sq + row_lo) << 10) + h * HD + d;
        size_t i1 = (((size_t)b * Sq + row_hi) << 10) + h * HD + d;
        *(uint32_t*)&g_ctx[i0] = pack_h2(o[ni][0] * inv_lo, o[ni][1] * inv_lo);
        *(uint32_t*)&g_ctx[i1] = pack_h2(o[ni][2] * inv_hi, o[ni][3] * inv_hi);
    }
}

// ---------------------------------------------------------------------------
// Launch
// ---------------------------------------------------------------------------
extern "C" void kernel_launch(void* const* d_in, const int* in_sizes, int n_in,
                              void* d_out, int out_size)
{
    const float* X       = (const float*)d_in[0];
    const float* W_qkv   = (const float*)d_in[2];
    const float* b_qkv   = (const float*)d_in[3];
    const float* W_dense = (const float*)d_in[4];
    const float* b_dense = (const float*)d_in[5];
    float* out = (float*)d_out;

    (void)in_sizes; (void)n_in; (void)out_size;

    __half *p_Xh, *p_Wqt, *p_Wdt, *p_ctx;
    cudaGetSymbolAddress((void**)&p_Xh,  g_Xh);
    cudaGetSymbolAddress((void**)&p_Wqt, g_Wqt);
    cudaGetSymbolAddress((void**)&p_Wdt, g_Wdt);
    cudaGetSymbolAddress((void**)&p_ctx, g_ctx);

    cudaFuncSetAttribute(attn_h, cudaFuncAttributeMaxDynamicSharedMemorySize,
                         AT_WORDS * 4);

    // 0. prep: X -> half; W -> W^T half
    conv_h<<<(M1 * Hd / 4 + 255) / 256, 256>>>((const float4*)X, (uint2*)p_Xh, M1 * Hd / 4);
    transp_h<<<dim3(3 * Hd / 32, Hd / 32), dim3(32, 8)>>>(W_qkv, p_Wqt, Hd, 3 * Hd);
    transp_h<<<dim3(Hd / 32, Hd / 32), dim3(32, 8)>>>(W_dense, p_Wdt, Hd, Hd);

    // 1. QKV projection (fp16 mma) -> g_q (1/8 scaled), g_k, g_vT
    gemm_h<1><<<dim3(3 * Hd / 128, M1 / 128), 256>>>(p_Xh, p_Wqt, b_qkv, nullptr, 3 * Hd);

    // 2. fp16 tensor-core causal flash attention -> g_ctx (half)
    attn_h<<<dim3(16, BH), 256, AT_WORDS * 4>>>();

    // 3. output projection (fp16 mma) -> fp32 out
    gemm_h<0><<<dim3(Hd / 128, M1 / 128), 256>>>(p_ctx, p_Wdt, b_dense, out, Hd);
}

// round 8
// speedup vs baseline: 1.9818x; 1.4570x over previous
#include <cuda_runtime.h>
#include <cuda_fp16.h>
#include <cstdint>

// Problem constants
#define Bsz 4
#define Sq  2048
#define Hd  1024
#define NH  16
#define HD  64
#define BH  (Bsz*NH)          // 64
#define M1  (Bsz*Sq)          // 8192
#define QKV_STRIDE ((size_t)BH*Sq*HD) // 8388608 halves per tensor

// Scratch (__device__ globals)
__device__ __half g_q  [QKV_STRIDE];            // [BH][S][HD], pre-scaled 1/8
__device__ __half g_k  [QKV_STRIDE];            // [BH][S][HD]
__device__ __half g_vT [QKV_STRIDE];            // [BH][HD][S]  (transposed)
__device__ __half g_ctx[(size_t)M1 * Hd];       // [B][S][H]
__device__ __half g_Xh [(size_t)M1 * Hd];       // X as half
__device__ __half g_Wqt[(size_t)3 * Hd * Hd];   // W_qkv^T  [3072][1024]
__device__ __half g_Wdt[(size_t)Hd * Hd];       // W_dense^T [1024][1024]

// ---------------------------------------------------------------------------
// Helpers
// ---------------------------------------------------------------------------
__device__ __forceinline__ uint32_t pack_h2(float a, float b) {
    __half2 h = __floats2half2_rn(a, b);
    return *(uint32_t*)&h;
}
__device__ __forceinline__ void cp_async16(void* smem_dst, const void* gmem_src) {
    uint32_t s = (uint32_t)__cvta_generic_to_shared(smem_dst);
    asm volatile("cp.async.ca.shared.global [%0], [%1], 16;\n" :: "r"(s), "l"(gmem_src));
}
#define CP_COMMIT() asm volatile("cp.async.commit_group;\n")
#define CP_WAIT(n)  asm volatile("cp.async.wait_group %0;\n" :: "n"(n))

__device__ __forceinline__ void ldsm_x4(uint32_t& r0, uint32_t& r1,
                                        uint32_t& r2, uint32_t& r3, uint32_t saddr) {
    asm volatile("ldmatrix.sync.aligned.m8n8.x4.shared.b16 {%0,%1,%2,%3}, [%4];"
                 : "=r"(r0), "=r"(r1), "=r"(r2), "=r"(r3) : "r"(saddr));
}

// fp16 mma, fp32 accum. A row-major (4 regs), B col-major (2 regs).
#define MMA_F16(acc, a, b0, b1)                                                \
    asm volatile(                                                              \
        "mma.sync.aligned.m16n8k16.row.col.f32.f16.f16.f32 "                   \
        "{%0,%1,%2,%3}, {%4,%5,%6,%7}, {%8,%9}, {%0,%1,%2,%3};\n"              \
        : "+f"((acc)[0]), "+f"((acc)[1]), "+f"((acc)[2]), "+f"((acc)[3])       \
        : "r"((a)[0]), "r"((a)[1]), "r"((a)[2]), "r"((a)[3]),                  \
          "r"(b0), "r"(b1))

// ---------------------------------------------------------------------------
// Prep: X fp32 -> half;  W fp32 [R][C] -> W^T half [C][R]
// ---------------------------------------------------------------------------
__global__ void conv_h(const float4* __restrict__ src, uint2* __restrict__ dst, int n4) {
    int i = blockIdx.x * blockDim.x + threadIdx.x;
    if (i < n4) {
        float4 v = src[i];
        dst[i] = make_uint2(pack_h2(v.x, v.y), pack_h2(v.z, v.w));
    }
}
__global__ void transp_h(const float* __restrict__ src, __half* __restrict__ dst,
                         int R, int C) {
    __shared__ __half t[32][33];
    int c0 = blockIdx.x * 32, r0 = blockIdx.y * 32;
    int tx = threadIdx.x, ty = threadIdx.y;   // 32 x 8
#pragma unroll
    for (int i = 0; i < 32; i += 8)
        t[ty + i][tx] = __float2half_rn(src[(size_t)(r0 + ty + i) * C + c0 + tx]);
    __syncthreads();
#pragma unroll
    for (int i = 0; i < 32; i += 8)
        dst[(size_t)(c0 + ty + i) * R + r0 + tx] = t[tx][ty + i];
}

// ---------------------------------------------------------------------------
// FP16 GEMM: C[M,N] = A[M,1024] @ Bw^T + bias.
// Block tile 128x256x32, 8 warps (2x4), warp tile 64x64, ldmatrix fragments,
// cp.async double buffer. Smem row stride 40 halves (80B; LDSM conflict-free).
// MODE 0: fp32 row-major C.  MODE 1: scatter to g_q(1/8)/g_k/g_vT.
// ---------------------------------------------------------------------------
#define G_STG_H 15360                     // halves per stage: 128*40 + 256*40
#define G_SMEM  (2 * G_STG_H * 2)         // 61440 bytes

template<int MODE>
__global__ __launch_bounds__(256)
void gemm_h(const __half* __restrict__ A, const __half* __restrict__ Bw,
            const float* __restrict__ bias, float* __restrict__ C, int N)
{
    extern __shared__ __half gsm[];

    const int tid  = threadIdx.x;
    const int lane = tid & 31;
    const int warp = tid >> 5;
    const int wm   = (warp >> 2) * 64;    // 0 or 64
    const int wn   = (warp & 3) * 64;     // 0..192
    const int brow = blockIdx.y * 128;
    const int bcol = blockIdx.x * 256;
    const int lg = lane >> 2;
    const int lt = lane & 3;

    // ldmatrix per-lane byte offsets (stride 80B rows)
    const uint32_t a_off = (uint32_t)((lane & 15) * 80 + (lane >> 4) * 16);
    const uint32_t b_off = (uint32_t)((((lane >> 4) * 8) + (lane & 7)) * 80
                                      + ((lane >> 3) & 1) * 16);

    uint32_t sbase = (uint32_t)__cvta_generic_to_shared(gsm);
    uint32_t aS[2] = { sbase,               sbase + G_STG_H * 2 };
    uint32_t bS[2] = { sbase + 5120 * 2,    sbase + (G_STG_H + 5120) * 2 };

    // loaders: A 512 chunks (2/thread), B 1024 chunks (4/thread)
    auto fill = [&](int k0, int st) {
        __half* Abuf = gsm + st * G_STG_H;
        __half* Bbuf = Abuf + 5120;
#pragma unroll
        for (int i = 0; i < 2; i++) {
            int c = tid + i * 256, r = c >> 2, sg = c & 3;
            cp_async16(&Abuf[r * 40 + sg * 8], A + (size_t)(brow + r) * 1024 + k0 + sg * 8);
        }
#pragma unroll
        for (int i = 0; i < 4; i++) {
            int c = tid + i * 256, r = c >> 2, sg = c & 3;
            cp_async16(&Bbuf[r * 40 + sg * 8], Bw + (size_t)(bcol + r) * 1024 + k0 + sg * 8);
        }
        CP_COMMIT();
    };

    float acc[4][8][4];
#pragma unroll
    for (int mi = 0; mi < 4; mi++)
#pragma unroll
        for (int ni = 0; ni < 8; ni++)
#pragma unroll
            for (int r = 0; r < 4; r++) acc[mi][ni][r] = 0.f;

    fill(0, 0);
    int buf = 0;
    const int NIT = 1024 / 32;
    for (int it = 0; it < NIT; ++it) {
        if (it + 1 < NIT) { fill((it + 1) * 32, buf ^ 1); CP_WAIT(1); }
        else CP_WAIT(0);
        __syncthreads();

#pragma unroll
        for (int ks = 0; ks < 2; ++ks) {
            uint32_t af[4][4], bf[8][2];
#pragma unroll
            for (int mi = 0; mi < 4; mi++)
                ldsm_x4(af[mi][0], af[mi][1], af[mi][2], af[mi][3],
                        aS[buf] + (wm + mi * 16) * 80 + ks * 32 + a_off);
#pragma unroll
            for (int nj = 0; nj < 8; nj += 2)
                ldsm_x4(bf[nj][0], bf[nj][1], bf[nj + 1][0], bf[nj + 1][1],
                        bS[buf] + (wn + nj * 8) * 80 + ks * 32 + b_off);
#pragma unroll
            for (int mi = 0; mi < 4; mi++)
#pragma unroll
                for (int ni = 0; ni < 8; ni++)
                    MMA_F16(acc[mi][ni], af[mi], bf[ni][0], bf[ni][1]);
        }
        __syncthreads();
        buf ^= 1;
    }

    // epilogue
#pragma unroll
    for (int mi = 0; mi < 4; mi++) {
#pragma unroll
        for (int ni = 0; ni < 8; ni++) {
            int gr = brow + wm + mi * 16 + lg;
            int gc = bcol + wn + ni * 8 + lt * 2;
            float bx = bias[gc], by = bias[gc + 1];
            float2 v0 = make_float2(acc[mi][ni][0] + bx, acc[mi][ni][1] + by);
            float2 v1 = make_float2(acc[mi][ni][2] + bx, acc[mi][ni][3] + by);
            if (MODE == 0) {
                *(float2*)&C[(size_t)gr * N + gc]       = v0;
                *(float2*)&C[(size_t)(gr + 8) * N + gc] = v1;
            } else {
                int which = gc >> 10;
                int hh    = (gc >> 6) & 15;
                int d     = gc & 63;
#pragma unroll
                for (int rr = 0; rr < 2; rr++) {
                    int row = gr + rr * 8;
                    int b   = row >> 11;
                    int s   = row & 2047;
                    int bh  = b * NH + hh;
                    float2 v = rr ? v1 : v0;
                    if (which == 0) {
                        *(uint32_t*)&g_q[((size_t)bh * Sq + s) * HD + d] =
                            pack_h2(v.x * 0.125f, v.y * 0.125f);
                    } else if (which == 1) {
                        *(uint32_t*)&g_k[((size_t)bh * Sq + s) * HD + d] =
                            pack_h2(v.x, v.y);
                    } else {
                        g_vT[((size_t)bh * HD + d)     * Sq + s] = __float2half_rn(v.x);
                        g_vT[((size_t)bh * HD + d + 1) * Sq + s] = __float2half_rn(v.y);
                    }
                }
            }
        }
    }
}

// ---------------------------------------------------------------------------
// FP16 causal flash attention with ldmatrix fragments.
// BM=128 (8 warps x 16 rows), BN=64, HD=64. Q frags in regs; Ps aliases Qs.
// Rows 36 words (144B): LDSM conflict-free ((9r)%8 = r%8 distinct).
// ---------------------------------------------------------------------------
#define AQ_W (128 * 36)
#define AK_W (64 * 36)
#define AT_WORDS (AQ_W + 4 * AK_W)   // 13824 words = 55296 B

__global__ __launch_bounds__(256)
void attn_h()
{
    extern __shared__ uint32_t sm[];
    uint32_t* Qs  = sm;
    uint32_t* Kb[2]  = { sm + AQ_W,            sm + AQ_W + 2 * AK_W };
    uint32_t* Vb[2]  = { sm + AQ_W + AK_W,     sm + AQ_W + 3 * AK_W };

    const int tid  = threadIdx.x;
    const int lane = tid & 31;
    const int warp = tid >> 5;
    const int lg = lane >> 2;
    const int lt = lane & 3;
    const int qt = 15 - blockIdx.x;
    const int bh = blockIdx.y;
    const int q0 = qt * 128;
    const int wm = warp * 16;

    // LDSM per-lane byte offsets (stride 144B rows)
    const uint32_t a_off = (uint32_t)((lane & 15) * 144 + (lane >> 4) * 16);
    const uint32_t b_off = (uint32_t)((((lane >> 4) * 8) + (lane & 7)) * 144
                                      + ((lane >> 3) & 1) * 16);

    const uint32_t qs_a = (uint32_t)__cvta_generic_to_shared(Qs);
    const uint32_t kb_a[2] = { (uint32_t)__cvta_generic_to_shared(Kb[0]),
                               (uint32_t)__cvta_generic_to_shared(Kb[1]) };
    const uint32_t vb_a[2] = { (uint32_t)__cvta_generic_to_shared(Vb[0]),
                               (uint32_t)__cvta_generic_to_shared(Vb[1]) };

    // Q load
    const __half* q_ptr = g_q + ((size_t)bh * Sq + q0) * HD;
#pragma unroll
    for (int i = 0; i < 4; i++) {
        int id = tid + i * 256;
        int row = id >> 3, seg = id & 7;
        cp_async16((char*)&Qs[row * 36] + seg * 16, q_ptr + (size_t)row * HD + seg * 8);
    }
    CP_COMMIT();

    auto load_kv = [&](int kt, int b) {
        const __half* k_ptr = g_k  + ((size_t)bh * Sq + kt * 64) * HD;
        const __half* v_ptr = g_vT + (size_t)bh * HD * Sq + kt * 64;
#pragma unroll
        for (int i = 0; i < 2; i++) {
            int id = tid + i * 256;
            int row = id >> 3, seg = id & 7;
            cp_async16((char*)&Kb[b][row * 36] + seg * 16, k_ptr + (size_t)row * HD + seg * 8);
            cp_async16((char*)&Vb[b][row * 36] + seg * 16, v_ptr + (size_t)row * Sq + seg * 8);
        }
        CP_COMMIT();
    };
    load_kv(0, 0);

    CP_WAIT(1);
    __syncthreads();

    // Q fragments via ldmatrix
    uint32_t qf[4][4];
#pragma unroll
    for (int ks = 0; ks < 4; ks++)
        ldsm_x4(qf[ks][0], qf[ks][1], qf[ks][2], qf[ks][3],
                qs_a + wm * 144 + ks * 32 + a_off);
    uint32_t* Ps = Qs;
    const uint32_t ps_a = qs_a;

    float m_lo = -1e30f, m_hi = -1e30f, l_lo = 0.f, l_hi = 0.f;
    float o[8][4];
#pragma unroll
    for (int ni = 0; ni < 8; ni++)
#pragma unroll
        for (int c = 0; c < 4; c++) o[ni][c] = 0.f;

    const int row_lo = q0 + wm + lg;
    const int row_hi = row_lo + 8;
    const int nkt = 2 * qt + 2;

    for (int kt = 0; kt < nkt; kt++) {
        const int p = kt & 1;
        CP_WAIT(0);
        __syncthreads();
        if (kt + 1 < nkt) load_kv(kt + 1, p ^ 1);

        // S = Q @ K^T
        float s[8][4];
#pragma unroll
        for (int ni = 0; ni < 8; ni++)
#pragma unroll
            for (int c = 0; c < 4; c++) s[ni][c] = 0.f;

#pragma unroll
        for (int ks = 0; ks < 4; ks++) {
            uint32_t bf[8][2];
#pragma unroll
            for (int nj = 0; nj < 8; nj += 2)
                ldsm_x4(bf[nj][0], bf[nj][1], bf[nj + 1][0], bf[nj + 1][1],
                        kb_a[p] + (nj * 8) * 144 + ks * 32 + b_off);
#pragma unroll
            for (int ni = 0; ni < 8; ni++)
                MMA_F16(s[ni], qf[ks], bf[ni][0], bf[ni][1]);
        }

        if (kt >= 2 * qt) {
            const int colb = kt * 64;
#pragma unroll
            for (int ni = 0; ni < 8; ni++) {
                int c0 = colb + ni * 8 + lt * 2;
                if (c0 > row_lo)     s[ni][0] = -1e30f;
                if (c0 + 1 > row_lo) s[ni][1] = -1e30f;
                if (c0 > row_hi)     s[ni][2] = -1e30f;
                if (c0 + 1 > row_hi) s[ni][3] = -1e30f;
            }
        }

        // online softmax (reg stats, quad reduce)
        float rx_lo = -1e30f, rx_hi = -1e30f;
#pragma unroll
        for (int ni = 0; ni < 8; ni++) {
            rx_lo = fmaxf(rx_lo, fmaxf(s[ni][0], s[ni][1]));
            rx_hi = fmaxf(rx_hi, fmaxf(s[ni][2], s[ni][3]));
        }
        rx_lo = fmaxf(rx_lo, __shfl_xor_sync(0xffffffffu, rx_lo, 1));
        rx_lo = fmaxf(rx_lo, __shfl_xor_sync(0xffffffffu, rx_lo, 2));
        rx_hi = fmaxf(rx_hi, __shfl_xor_sync(0xffffffffu, rx_hi, 1));
        rx_hi = fmaxf(rx_hi, __shfl_xor_sync(0xffffffffu, rx_hi, 2));

        float mn_lo = fmaxf(m_lo, rx_lo);
        float mn_hi = fmaxf(m_hi, rx_hi);
        float al_lo = __expf(m_lo - mn_lo);
        float al_hi = __expf(m_hi - mn_hi);
        m_lo = mn_lo; m_hi = mn_hi;

        float rs_lo = 0.f, rs_hi = 0.f;
#pragma unroll
        for (int ni = 0; ni < 8; ni++) {
            s[ni][0] = __expf(s[ni][0] - mn_lo);
            s[ni][1] = __expf(s[ni][1] - mn_lo);
            s[ni][2] = __expf(s[ni][2] - mn_hi);
            s[ni][3] = __expf(s[ni][3] - mn_hi);
            rs_lo += s[ni][0] + s[ni][1];
            rs_hi += s[ni][2] + s[ni][3];
        }
        rs_lo += __shfl_xor_sync(0xffffffffu, rs_lo, 1);
        rs_lo += __shfl_xor_sync(0xffffffffu, rs_lo, 2);
        rs_hi += __shfl_xor_sync(0xffffffffu, rs_hi, 1);
        rs_hi += __shfl_xor_sync(0xffffffffu, rs_hi, 2);
        l_lo = l_lo * al_lo + rs_lo;
        l_hi = l_hi * al_hi + rs_hi;

#pragma unroll
        for (int ni = 0; ni < 8; ni++) {
            o[ni][0] *= al_lo; o[ni][1] *= al_lo;
            o[ni][2] *= al_hi; o[ni][3] *= al_hi;
        }

        // P (half2) into warp-private Ps rows
#pragma unroll
        for (int ni = 0; ni < 8; ni++) {
            Ps[(wm + lg) * 36 + ni * 4 + lt]     = pack_h2(s[ni][0], s[ni][1]);
            Ps[(wm + lg + 8) * 36 + ni * 4 + lt] = pack_h2(s[ni][2], s[ni][3]);
        }
        __syncwarp();

        // O += P @ V   (V^T tile: rows = d, cols = keys)
#pragma unroll
        for (int ks = 0; ks < 4; ks++) {
            uint32_t pf[4];
            ldsm_x4(pf[0], pf[1], pf[2], pf[3],
                    ps_a + wm * 144 + ks * 32 + a_off);
            uint32_t bf[8][2];
#pragma unroll
            for (int nj = 0; nj < 8; nj += 2)
                ldsm_x4(bf[nj][0], bf[nj][1], bf[nj + 1][0], bf[nj + 1][1],
                        vb_a[p] + (nj * 8) * 144 + ks * 32 + b_off);
#pragma unroll
            for (int ni = 0; ni < 8; ni++)
                MMA_F16(o[ni], pf, bf[ni][0], bf[ni][1]);
        }
        __syncwarp();
    }

    // epilogue: normalize, write ctx as half
    const int b = bh >> 4;
    const int h = bh & 15;
    const float inv_lo = 1.f / l_lo;
    const float inv_hi = 1.f / l_hi;
#pragma unroll
    for (int ni = 0; ni < 8; ni++) {
        int d = ni * 8 + lt * 2;
        size_t i0 = (((size_t)b * Sq + row_lo) << 10) + h * HD + d;
        size_t i1 = (((size_t)b * Sq + row_hi) << 10) + h * HD + d;
        *(uint32_t*)&g_ctx[i0] = pack_h2(o[ni][0] * inv_lo, o[ni][1] * inv_lo);
        *(uint32_t*)&g_ctx[i1] = pack_h2(o[ni][2] * inv_hi, o[ni][3] * inv_hi);
    }
}

// ---------------------------------------------------------------------------
// Launch
// ---------------------------------------------------------------------------
extern "C" void kernel_launch(void* const* d_in, const int* in_sizes, int n_in,
                              void* d_out, int out_size)
{
    const float* X       = (const float*)d_in[0];
    const float* W_qkv   = (const float*)d_in[2];
    const float* b_qkv   = (const float*)d_in[3];
    const float* W_dense = (const float*)d_in[4];
    const float* b_dense = (const float*)d_in[5];
    float* out = (float*)d_out;

    (void)in_sizes; (void)n_in; (void)out_size;

    __half *p_Xh, *p_Wqt, *p_Wdt, *p_ctx;
    cudaGetSymbolAddress((void**)&p_Xh,  g_Xh);
    cudaGetSymbolAddress((void**)&p_Wqt, g_Wqt);
    cudaGetSymbolAddress((void**)&p_Wdt, g_Wdt);
    cudaGetSymbolAddress((void**)&p_ctx, g_ctx);

    cudaFuncSetAttribute(gemm_h<1>, cudaFuncAttributeMaxDynamicSharedMemorySize, G_SMEM);
    cudaFuncSetAttribute(gemm_h<0>, cudaFuncAttributeMaxDynamicSharedMemorySize, G_SMEM);
    cudaFuncSetAttribute(attn_h, cudaFuncAttributeMaxDynamicSharedMemorySize, AT_WORDS * 4);

    // 0. prep: X -> half; W -> W^T half
    conv_h<<<(M1 * Hd / 4 + 255) / 256, 256>>>((const float4*)X, (uint2*)p_Xh, M1 * Hd / 4);
    transp_h<<<dim3(3 * Hd / 32, Hd / 32), dim3(32, 8)>>>(W_qkv, p_Wqt, Hd, 3 * Hd);
    transp_h<<<dim3(Hd / 32, Hd / 32), dim3(32, 8)>>>(W_dense, p_Wdt, Hd, Hd);

    // 1. QKV projection -> g_q (1/8 scaled), g_k, g_vT
    gemm_h<1><<<dim3(3 * Hd / 256, M1 / 128), 256, G_SMEM>>>(p_Xh, p_Wqt, b_qkv, nullptr, 3 * Hd);

    // 2. fp16 causal flash attention -> g_ctx (half)
    attn_h<<<dim3(16, BH), 256, AT_WORDS * 4>>>();

    // 3. output projection -> fp32 out
    gemm_h<0><<<dim3(Hd / 256, M1 / 128), 256, G_SMEM>>>(p_ctx, p_Wdt, b_dense, out, Hd);
}

// round 9
// speedup vs baseline: 2.3238x; 1.1726x over previous
#include <cuda_runtime.h>
#include <cuda_fp16.h>
#include <cstdint>

// Problem constants
#define Bsz 4
#define Sq  2048
#define Hd  1024
#define NH  16
#define HD  64
#define BH  (Bsz*NH)          // 64
#define M1  (Bsz*Sq)          // 8192
#define QKV_STRIDE ((size_t)BH*Sq*HD) // 8388608 halves per tensor

// Scratch (__device__ globals)
__device__ __half g_q  [QKV_STRIDE];            // [BH][S][HD], pre-scaled 1/8
__device__ __half g_k  [QKV_STRIDE];            // [BH][S][HD]
__device__ __half g_vT [QKV_STRIDE];            // [BH][HD][S]  (transposed)
__device__ __half g_ctx[(size_t)M1 * Hd];       // [B][S][H]
__device__ __half g_Xh [(size_t)M1 * Hd];       // X as half
__device__ __half g_Wqt[(size_t)3 * Hd * Hd];   // W_qkv^T  [3072][1024]
__device__ __half g_Wdt[(size_t)Hd * Hd];       // W_dense^T [1024][1024]

// ---------------------------------------------------------------------------
// Helpers
// ---------------------------------------------------------------------------
__device__ __forceinline__ uint32_t pack_h2(float a, float b) {
    __half2 h = __floats2half2_rn(a, b);
    return *(uint32_t*)&h;
}
__device__ __forceinline__ void cp_async16(void* smem_dst, const void* gmem_src) {
    uint32_t s = (uint32_t)__cvta_generic_to_shared(smem_dst);
    asm volatile("cp.async.cg.shared.global [%0], [%1], 16;\n" :: "r"(s), "l"(gmem_src));
}
#define CP_COMMIT() asm volatile("cp.async.commit_group;\n")
#define CP_WAIT(n)  asm volatile("cp.async.wait_group %0;\n" :: "n"(n))

__device__ __forceinline__ void ldsm_x4(uint32_t& r0, uint32_t& r1,
                                        uint32_t& r2, uint32_t& r3, uint32_t saddr) {
    asm volatile("ldmatrix.sync.aligned.m8n8.x4.shared.b16 {%0,%1,%2,%3}, [%4];"
                 : "=r"(r0), "=r"(r1), "=r"(r2), "=r"(r3) : "r"(saddr));
}

// fp16 mma, fp32 accum. A row-major (4 regs), B col-major (2 regs).
#define MMA_F16(acc, a, b0, b1)                                                \
    asm volatile(                                                              \
        "mma.sync.aligned.m16n8k16.row.col.f32.f16.f16.f32 "                   \
        "{%0,%1,%2,%3}, {%4,%5,%6,%7}, {%8,%9}, {%0,%1,%2,%3};\n"              \
        : "+f"((acc)[0]), "+f"((acc)[1]), "+f"((acc)[2]), "+f"((acc)[3])       \
        : "r"((a)[0]), "r"((a)[1]), "r"((a)[2]), "r"((a)[3]),                  \
          "r"(b0), "r"(b1))

// ---------------------------------------------------------------------------
// Prep: X fp32 -> half;  W fp32 [R][C] -> W^T half [C][R]
// ---------------------------------------------------------------------------
__global__ void conv_h(const float4* __restrict__ src, uint2* __restrict__ dst, int n4) {
    int i = blockIdx.x * blockDim.x + threadIdx.x;
    if (i < n4) {
        float4 v = src[i];
        dst[i] = make_uint2(pack_h2(v.x, v.y), pack_h2(v.z, v.w));
    }
}
__global__ void transp_h(const float* __restrict__ src, __half* __restrict__ dst,
                         int R, int C) {
    __shared__ __half t[32][33];
    int c0 = blockIdx.x * 32, r0 = blockIdx.y * 32;
    int tx = threadIdx.x, ty = threadIdx.y;   // 32 x 8
#pragma unroll
    for (int i = 0; i < 32; i += 8)
        t[ty + i][tx] = __float2half_rn(src[(size_t)(r0 + ty + i) * C + c0 + tx]);
    __syncthreads();
#pragma unroll
    for (int i = 0; i < 32; i += 8)
        dst[(size_t)(c0 + ty + i) * R + r0 + tx] = t[tx][ty + i];
}

// ---------------------------------------------------------------------------
// FP16 GEMM: C[M,N] = A[M,1024] @ Bw^T + bias.
// Block tile 128x256, K-chunk 64, 3-stage cp.async ring, ONE sync per iter.
// 8 warps (2x4), warp tile 64x64, ldmatrix fragments.
// Smem rows 72 halves (144B stride; LDSM conflict-free).
// MODE 0: fp32 row-major C.  MODE 1: scatter to g_q(1/8)/g_k/g_vT.
// ---------------------------------------------------------------------------
#define G_AROWS 128
#define G_BROWS 256
#define G_STG_H ((G_AROWS + G_BROWS) * 72)   // 27648 halves per stage
#define G_SMEM  (3 * G_STG_H * 2)            // 165888 bytes

template<int MODE>
__global__ __launch_bounds__(256)
void gemm_h(const __half* __restrict__ A, const __half* __restrict__ Bw,
            const float* __restrict__ bias, float* __restrict__ C, int N)
{
    extern __shared__ __half gsm[];

    const int tid  = threadIdx.x;
    const int lane = tid & 31;
    const int warp = tid >> 5;
    const int wm   = (warp >> 2) * 64;    // 0 or 64
    const int wn   = (warp & 3) * 64;     // 0..192
    const int brow = blockIdx.y * 128;
    const int bcol = blockIdx.x * 256;
    const int lg = lane >> 2;
    const int lt = lane & 3;

    // ldmatrix per-lane byte offsets (144B row stride)
    const uint32_t a_off = (uint32_t)((lane & 15) * 144 + (lane >> 4) * 16);
    const uint32_t b_off = (uint32_t)((((lane >> 4) * 8) + (lane & 7)) * 144
                                      + ((lane >> 3) & 1) * 16);

    const uint32_t sbase = (uint32_t)__cvta_generic_to_shared(gsm);

    // fill stage st with K-chunk [k0, k0+64)
    auto fill = [&](int k0, int st) {
        __half* Abuf = gsm + st * G_STG_H;
        __half* Bbuf = Abuf + G_AROWS * 72;
#pragma unroll
        for (int i = 0; i < 4; i++) {          // A: 128 rows x 128B
            int c = tid + i * 256, r = c >> 3, sg = c & 7;
            cp_async16(&Abuf[r * 72 + sg * 8], A + (size_t)(brow + r) * 1024 + k0 + sg * 8);
        }
#pragma unroll
        for (int i = 0; i < 8; i++) {          // B: 256 rows x 128B
            int c = tid + i * 256, r = c >> 3, sg = c & 7;
            cp_async16(&Bbuf[r * 72 + sg * 8], Bw + (size_t)(bcol + r) * 1024 + k0 + sg * 8);
        }
        CP_COMMIT();
    };

    float acc[4][8][4];
#pragma unroll
    for (int mi = 0; mi < 4; mi++)
#pragma unroll
        for (int ni = 0; ni < 8; ni++)
#pragma unroll
            for (int r = 0; r < 4; r++) acc[mi][ni][r] = 0.f;

    const int NIT = 1024 / 64;   // 16
    fill(0, 0);
    fill(64, 1);

    for (int it = 0; it < NIT; ++it) {
        if (it == NIT - 1) CP_WAIT(0); else CP_WAIT(1);
        __syncthreads();
        if (it + 2 < NIT) fill((it + 2) * 64, (it + 2) % 3);

        const int st = it % 3;
        const uint32_t aS = sbase + st * G_STG_H * 2;
        const uint32_t bS = aS + G_AROWS * 72 * 2;

#pragma unroll
        for (int ks = 0; ks < 4; ++ks) {
            uint32_t af[4][4], bf[8][2];
#pragma unroll
            for (int mi = 0; mi < 4; mi++)
                ldsm_x4(af[mi][0], af[mi][1], af[mi][2], af[mi][3],
                        aS + (wm + mi * 16) * 144 + ks * 32 + a_off);
#pragma unroll
            for (int nj = 0; nj < 8; nj += 2)
                ldsm_x4(bf[nj][0], bf[nj][1], bf[nj + 1][0], bf[nj + 1][1],
                        bS + (wn + nj * 8) * 144 + ks * 32 + b_off);
#pragma unroll
            for (int mi = 0; mi < 4; mi++)
#pragma unroll
                for (int ni = 0; ni < 8; ni++)
                    MMA_F16(acc[mi][ni], af[mi], bf[ni][0], bf[ni][1]);
        }
    }
    __syncthreads();   // all MMA reads done before any smem reuse (none, but safe)

    // epilogue
#pragma unroll
    for (int mi = 0; mi < 4; mi++) {
#pragma unroll
        for (int ni = 0; ni < 8; ni++) {
            int gr = brow + wm + mi * 16 + lg;
            int gc = bcol + wn + ni * 8 + lt * 2;
            float bx = bias[gc], by = bias[gc + 1];
            float2 v0 = make_float2(acc[mi][ni][0] + bx, acc[mi][ni][1] + by);
            float2 v1 = make_float2(acc[mi][ni][2] + bx, acc[mi][ni][3] + by);
            if (MODE == 0) {
                *(float2*)&C[(size_t)gr * N + gc]       = v0;
                *(float2*)&C[(size_t)(gr + 8) * N + gc] = v1;
            } else {
                int which = gc >> 10;
                int hh    = (gc >> 6) & 15;
                int d     = gc & 63;
#pragma unroll
                for (int rr = 0; rr < 2; rr++) {
                    int row = gr + rr * 8;
                    int b   = row >> 11;
                    int s   = row & 2047;
                    int bh  = b * NH + hh;
                    float2 v = rr ? v1 : v0;
                    if (which == 0) {
                        *(uint32_t*)&g_q[((size_t)bh * Sq + s) * HD + d] =
                            pack_h2(v.x * 0.125f, v.y * 0.125f);
                    } else if (which == 1) {
                        *(uint32_t*)&g_k[((size_t)bh * Sq + s) * HD + d] =
                            pack_h2(v.x, v.y);
                    } else {
                        g_vT[((size_t)bh * HD + d)     * Sq + s] = __float2half_rn(v.x);
                        g_vT[((size_t)bh * HD + d + 1) * Sq + s] = __float2half_rn(v.y);
                    }
                }
            }
        }
    }
}

// ---------------------------------------------------------------------------
// FP16 causal flash attention. BM=128 (8 warps x 16 rows), BN=64, HD=64.
// Q frags in regs; P stays ENTIRELY in registers (QK D-frag == PV A-frag
// layout), no smem round-trip. K/V double-buffered, ldmatrix B-frags.
// Rows 36 words (144B): LDSM conflict-free.
// ---------------------------------------------------------------------------
#define AQ_W (128 * 36)
#define AK_W (64 * 36)
#define AT_WORDS (AQ_W + 4 * AK_W)   // 13824 words = 55296 B

__global__ __launch_bounds__(256)
void attn_h()
{
    extern __shared__ uint32_t sm[];
    uint32_t* Qs  = sm;
    uint32_t* Kb[2]  = { sm + AQ_W,            sm + AQ_W + 2 * AK_W };
    uint32_t* Vb[2]  = { sm + AQ_W + AK_W,     sm + AQ_W + 3 * AK_W };

    const int tid  = threadIdx.x;
    const int lane = tid & 31;
    const int warp = tid >> 5;
    const int lg = lane >> 2;
    const int lt = lane & 3;
    const int qt = 15 - blockIdx.x;     // heavy tiles first
    const int bh = blockIdx.y;
    const int q0 = qt * 128;
    const int wm = warp * 16;

    const uint32_t a_off = (uint32_t)((lane & 15) * 144 + (lane >> 4) * 16);
    const uint32_t b_off = (uint32_t)((((lane >> 4) * 8) + (lane & 7)) * 144
                                      + ((lane >> 3) & 1) * 16);

    const uint32_t qs_a = (uint32_t)__cvta_generic_to_shared(Qs);
    const uint32_t kb_a[2] = { (uint32_t)__cvta_generic_to_shared(Kb[0]),
                               (uint32_t)__cvta_generic_to_shared(Kb[1]) };
    const uint32_t vb_a[2] = { (uint32_t)__cvta_generic_to_shared(Vb[0]),
                               (uint32_t)__cvta_generic_to_shared(Vb[1]) };

    // Q load
    const __half* q_ptr = g_q + ((size_t)bh * Sq + q0) * HD;
#pragma unroll
    for (int i = 0; i < 4; i++) {
        int id = tid + i * 256;
        int row = id >> 3, seg = id & 7;
        cp_async16((char*)&Qs[row * 36] + seg * 16, q_ptr + (size_t)row * HD + seg * 8);
    }
    CP_COMMIT();

    auto load_kv = [&](int kt, int b) {
        const __half* k_ptr = g_k  + ((size_t)bh * Sq + kt * 64) * HD;
        const __half* v_ptr = g_vT + (size_t)bh * HD * Sq + kt * 64;
#pragma unroll
        for (int i = 0; i < 2; i++) {
            int id = tid + i * 256;
            int row = id >> 3, seg = id & 7;
            cp_async16((char*)&Kb[b][row * 36] + seg * 16, k_ptr + (size_t)row * HD + seg * 8);
            cp_async16((char*)&Vb[b][row * 36] + seg * 16, v_ptr + (size_t)row * Sq + seg * 8);
        }
        CP_COMMIT();
    };
    load_kv(0, 0);

    CP_WAIT(1);
    __syncthreads();

    // Q fragments via ldmatrix (warp-private rows)
    uint32_t qf[4][4];
#pragma unroll
    for (int ks = 0; ks < 4; ks++)
        ldsm_x4(qf[ks][0], qf[ks][1], qf[ks][2], qf[ks][3],
                qs_a + wm * 144 + ks * 32 + a_off);

    float m_lo = -1e30f, m_hi = -1e30f, l_lo = 0.f, l_hi = 0.f;
    float o[8][4];
#pragma unroll
    for (int ni = 0; ni < 8; ni++)
#pragma unroll
        for (int c = 0; c < 4; c++) o[ni][c] = 0.f;

    const int row_lo = q0 + wm + lg;
    const int row_hi = row_lo + 8;
    const int nkt = 2 * qt + 2;

    for (int kt = 0; kt < nkt; kt++) {
        const int p = kt & 1;
        CP_WAIT(0);
        __syncthreads();
        if (kt + 1 < nkt) load_kv(kt + 1, p ^ 1);

        // S = Q @ K^T
        float s[8][4];
#pragma unroll
        for (int ni = 0; ni < 8; ni++)
#pragma unroll
            for (int c = 0; c < 4; c++) s[ni][c] = 0.f;

#pragma unroll
        for (int ks = 0; ks < 4; ks++) {
            uint32_t bf[8][2];
#pragma unroll
            for (int nj = 0; nj < 8; nj += 2)
                ldsm_x4(bf[nj][0], bf[nj][1], bf[nj + 1][0], bf[nj + 1][1],
                        kb_a[p] + (nj * 8) * 144 + ks * 32 + b_off);
#pragma unroll
            for (int ni = 0; ni < 8; ni++)
                MMA_F16(s[ni], qf[ks], bf[ni][0], bf[ni][1]);
        }

        if (kt >= 2 * qt) {
            const int colb = kt * 64;
#pragma unroll
            for (int ni = 0; ni < 8; ni++) {
                int c0 = colb + ni * 8 + lt * 2;
                if (c0 > row_lo)     s[ni][0] = -1e30f;
                if (c0 + 1 > row_lo) s[ni][1] = -1e30f;
                if (c0 > row_hi)     s[ni][2] = -1e30f;
                if (c0 + 1 > row_hi) s[ni][3] = -1e30f;
            }
        }

        // online softmax (reg stats, quad reduce)
        float rx_lo = -1e30f, rx_hi = -1e30f;
#pragma unroll
        for (int ni = 0; ni < 8; ni++) {
            rx_lo = fmaxf(rx_lo, fmaxf(s[ni][0], s[ni][1]));
            rx_hi = fmaxf(rx_hi, fmaxf(s[ni][2], s[ni][3]));
        }
        rx_lo = fmaxf(rx_lo, __shfl_xor_sync(0xffffffffu, rx_lo, 1));
        rx_lo = fmaxf(rx_lo, __shfl_xor_sync(0xffffffffu, rx_lo, 2));
        rx_hi = fmaxf(rx_hi, __shfl_xor_sync(0xffffffffu, rx_hi, 1));
        rx_hi = fmaxf(rx_hi, __shfl_xor_sync(0xffffffffu, rx_hi, 2));

        float mn_lo = fmaxf(m_lo, rx_lo);
        float mn_hi = fmaxf(m_hi, rx_hi);
        float al_lo = __expf(m_lo - mn_lo);
        float al_hi = __expf(m_hi - mn_hi);
        m_lo = mn_lo; m_hi = mn_hi;

        float rs_lo = 0.f, rs_hi = 0.f;
#pragma unroll
        for (int ni = 0; ni < 8; ni++) {
            s[ni][0] = __expf(s[ni][0] - mn_lo);
            s[ni][1] = __expf(s[ni][1] - mn_lo);
            s[ni][2] = __expf(s[ni][2] - mn_hi);
            s[ni][3] = __expf(s[ni][3] - mn_hi);
            rs_lo += s[ni][0] + s[ni][1];
            rs_hi += s[ni][2] + s[ni][3];
        }
        rs_lo += __shfl_xor_sync(0xffffffffu, rs_lo, 1);
        rs_lo += __shfl_xor_sync(0xffffffffu, rs_lo, 2);
        rs_hi += __shfl_xor_sync(0xffffffffu, rs_hi, 1);
        rs_hi += __shfl_xor_sync(0xffffffffu, rs_hi, 2);
        l_lo = l_lo * al_lo + rs_lo;
        l_hi = l_hi * al_hi + rs_hi;

#pragma unroll
        for (int ni = 0; ni < 8; ni++) {
            o[ni][0] *= al_lo; o[ni][1] *= al_lo;
            o[ni][2] *= al_hi; o[ni][3] *= al_hi;
        }

        // O += P @ V: P A-frags come DIRECTLY from the s registers
        // (QK D-frag layout == PV A-frag layout; ks covers keys 16ks..16ks+15)
#pragma unroll
        for (int ks = 0; ks < 4; ks++) {
            uint32_t pf[4];
            pf[0] = pack_h2(s[2 * ks][0],     s[2 * ks][1]);
            pf[1] = pack_h2(s[2 * ks][2],     s[2 * ks][3]);
            pf[2] = pack_h2(s[2 * ks + 1][0], s[2 * ks + 1][1]);
            pf[3] = pack_h2(s[2 * ks + 1][2], s[2 * ks + 1][3]);
            uint32_t bf[8][2];
#pragma unroll
            for (int nj = 0; nj < 8; nj += 2)
                ldsm_x4(bf[nj][0], bf[nj][1], bf[nj + 1][0], bf[nj + 1][1],
                        vb_a[p] + (nj * 8) * 144 + ks * 32 + b_off);
#pragma unroll
            for (int ni = 0; ni < 8; ni++)
                MMA_F16(o[ni], pf, bf[ni][0], bf[ni][1]);
        }
    }

    // epilogue: normalize, write ctx as half
    const int b = bh >> 4;
    const int h = bh & 15;
    const float inv_lo = 1.f / l_lo;
    const float inv_hi = 1.f / l_hi;
#pragma unroll
    for (int ni = 0; ni < 8; ni++) {
        int d = ni * 8 + lt * 2;
        size_t i0 = (((size_t)b * Sq + row_lo) << 10) + h * HD + d;
        size_t i1 = (((size_t)b * Sq + row_hi) << 10) + h * HD + d;
        *(uint32_t*)&g_ctx[i0] = pack_h2(o[ni][0] * inv_lo, o[ni][1] * inv_lo);
        *(uint32_t*)&g_ctx[i1] = pack_h2(o[ni][2] * inv_hi, o[ni][3] * inv_hi);
    }
}

// ---------------------------------------------------------------------------
// Launch
// ---------------------------------------------------------------------------
extern "C" void kernel_launch(void* const* d_in, const int* in_sizes, int n_in,
                              void* d_out, int out_size)
{
    const float* X       = (const float*)d_in[0];
    const float* W_qkv   = (const float*)d_in[2];
    const float* b_qkv   = (const float*)d_in[3];
    const float* W_dense = (const float*)d_in[4];
    const float* b_dense = (const float*)d_in[5];
    float* out = (float*)d_out;

    (void)in_sizes; (void)n_in; (void)out_size;

    __half *p_Xh, *p_Wqt, *p_Wdt, *p_ctx;
    cudaGetSymbolAddress((void**)&p_Xh,  g_Xh);
    cudaGetSymbolAddress((void**)&p_Wqt, g_Wqt);
    cudaGetSymbolAddress((void**)&p_Wdt, g_Wdt);
    cudaGetSymbolAddress((void**)&p_ctx, g_ctx);

    cudaFuncSetAttribute(gemm_h<1>, cudaFuncAttributeMaxDynamicSharedMemorySize, G_SMEM);
    cudaFuncSetAttribute(gemm_h<0>, cudaFuncAttributeMaxDynamicSharedMemorySize, G_SMEM);
    cudaFuncSetAttribute(attn_h, cudaFuncAttributeMaxDynamicSharedMemorySize, AT_WORDS * 4);

    // 0. prep: X -> half; W -> W^T half
    conv_h<<<(M1 * Hd / 4 + 255) / 256, 256>>>((const float4*)X, (uint2*)p_Xh, M1 * Hd / 4);
    transp_h<<<dim3(3 * Hd / 32, Hd / 32), dim3(32, 8)>>>(W_qkv, p_Wqt, Hd, 3 * Hd);
    transp_h<<<dim3(Hd / 32, Hd / 32), dim3(32, 8)>>>(W_dense, p_Wdt, Hd, Hd);

    // 1. QKV projection -> g_q (1/8 scaled), g_k, g_vT
    gemm_h<1><<<dim3(3 * Hd / 256, M1 / 128), 256, G_SMEM>>>(p_Xh, p_Wqt, b_qkv, nullptr, 3 * Hd);

    // 2. fp16 causal flash attention -> g_ctx (half)
    attn_h<<<dim3(16, BH), 256, AT_WORDS * 4>>>();

    // 3. output projection -> fp32 out
    gemm_h<0><<<dim3(Hd / 256, M1 / 128), 256, G_SMEM>>>(p_ctx, p_Wdt, b_dense, out, Hd);
}

// round 10
// speedup vs baseline: 2.4180x; 1.0405x over previous
#include <cuda_runtime.h>
#include <cuda_fp16.h>
#include <cstdint>

// Problem constants
#define Bsz 4
#define Sq  2048
#define Hd  1024
#define NH  16
#define HD  64
#define BH  (Bsz*NH)          // 64
#define M1  (Bsz*Sq)          // 8192
#define QKV_STRIDE ((size_t)BH*Sq*HD) // 8388608 halves per tensor

// Scratch (__device__ globals)
__device__ __half g_q  [QKV_STRIDE];            // [BH][S][HD], pre-scaled 1/8
__device__ __half g_k  [QKV_STRIDE];            // [BH][S][HD]
__device__ __half g_vT [QKV_STRIDE];            // [BH][HD][S]  (transposed)
__device__ __half g_ctx[(size_t)M1 * Hd];       // [B][S][H]
__device__ __half g_Xh [(size_t)M1 * Hd];       // X as half
__device__ __half g_Wqt[(size_t)3 * Hd * Hd];   // W_qkv^T  [3072][1024]
__device__ __half g_Wdt[(size_t)Hd * Hd];       // W_dense^T [1024][1024]

// ---------------------------------------------------------------------------
// Helpers
// ---------------------------------------------------------------------------
__device__ __forceinline__ uint32_t pack_h2(float a, float b) {
    __half2 h = __floats2half2_rn(a, b);
    return *(uint32_t*)&h;
}
__device__ __forceinline__ void cp_async16(void* smem_dst, const void* gmem_src) {
    uint32_t s = (uint32_t)__cvta_generic_to_shared(smem_dst);
    asm volatile("cp.async.cg.shared.global [%0], [%1], 16;\n" :: "r"(s), "l"(gmem_src));
}
#define CP_COMMIT() asm volatile("cp.async.commit_group;\n")
#define CP_WAIT(n)  asm volatile("cp.async.wait_group %0;\n" :: "n"(n))

__device__ __forceinline__ void ldsm_x4(uint32_t& r0, uint32_t& r1,
                                        uint32_t& r2, uint32_t& r3, uint32_t saddr) {
    asm volatile("ldmatrix.sync.aligned.m8n8.x4.shared.b16 {%0,%1,%2,%3}, [%4];"
                 : "=r"(r0), "=r"(r1), "=r"(r2), "=r"(r3) : "r"(saddr));
}

// fp16 mma, fp32 accum. A row-major (4 regs), B col-major (2 regs).
#define MMA_F16(acc, a, b0, b1)                                                \
    asm volatile(                                                              \
        "mma.sync.aligned.m16n8k16.row.col.f32.f16.f16.f32 "                   \
        "{%0,%1,%2,%3}, {%4,%5,%6,%7}, {%8,%9}, {%0,%1,%2,%3};\n"              \
        : "+f"((acc)[0]), "+f"((acc)[1]), "+f"((acc)[2]), "+f"((acc)[3])       \
        : "r"((a)[0]), "r"((a)[1]), "r"((a)[2]), "r"((a)[3]),                  \
          "r"(b0), "r"(b1))

// ---------------------------------------------------------------------------
// Prep: X fp32 -> half;  W fp32 [R][C] -> W^T half [C][R]
// ---------------------------------------------------------------------------
__global__ void conv_h(const float4* __restrict__ src, uint2* __restrict__ dst, int n4) {
    int i = blockIdx.x * blockDim.x + threadIdx.x;
    if (i < n4) {
        float4 v = src[i];
        dst[i] = make_uint2(pack_h2(v.x, v.y), pack_h2(v.z, v.w));
    }
}
__global__ void transp_h(const float* __restrict__ src, __half* __restrict__ dst,
                         int R, int C) {
    __shared__ __half t[32][33];
    int c0 = blockIdx.x * 32, r0 = blockIdx.y * 32;
    int tx = threadIdx.x, ty = threadIdx.y;   // 32 x 8
#pragma unroll
    for (int i = 0; i < 32; i += 8)
        t[ty + i][tx] = __float2half_rn(src[(size_t)(r0 + ty + i) * C + c0 + tx]);
    __syncthreads();
#pragma unroll
    for (int i = 0; i < 32; i += 8)
        dst[(size_t)(c0 + ty + i) * R + r0 + tx] = t[tx][ty + i];
}

// ---------------------------------------------------------------------------
// FP16 GEMM: C[M,N] = A[M,1024] @ Bw^T + bias.
// Block tile 128x128, 4 warps (2x2), warp tile 64x64. K-chunk 64,
// 3-stage cp.async ring, ONE sync per iter. 2 CTAs/SM (latency hiding).
// Smem rows 72 halves (144B stride; LDSM conflict-free).
// MODE 0: fp32 row-major C.  MODE 1: scatter to g_q(1/8)/g_k/g_vT.
// ---------------------------------------------------------------------------
#define G_ROWS 128
#define G_STG_H (2 * G_ROWS * 72)            // 18432 halves per stage (A+B)
#define G_SMEM  (3 * G_STG_H * 2)            // 110592 bytes

template<int MODE>
__global__ __launch_bounds__(128, 2)
void gemm_h(const __half* __restrict__ A, const __half* __restrict__ Bw,
            const float* __restrict__ bias, float* __restrict__ C, int N)
{
    extern __shared__ __half gsm[];

    const int tid  = threadIdx.x;
    const int lane = tid & 31;
    const int warp = tid >> 5;
    const int wm   = (warp >> 1) * 64;    // 0 or 64
    const int wn   = (warp & 1) * 64;     // 0 or 64
    const int brow = blockIdx.y * 128;
    const int bcol = blockIdx.x * 128;
    const int lg = lane >> 2;
    const int lt = lane & 3;

    // ldmatrix per-lane byte offsets (144B row stride)
    const uint32_t a_off = (uint32_t)((lane & 15) * 144 + (lane >> 4) * 16);
    const uint32_t b_off = (uint32_t)((((lane >> 4) * 8) + (lane & 7)) * 144
                                      + ((lane >> 3) & 1) * 16);

    const uint32_t sbase = (uint32_t)__cvta_generic_to_shared(gsm);

    // fill stage st with K-chunk [k0, k0+64)
    auto fill = [&](int k0, int st) {
        __half* Abuf = gsm + st * G_STG_H;
        __half* Bbuf = Abuf + G_ROWS * 72;
#pragma unroll
        for (int i = 0; i < 8; i++) {          // A: 128 rows x 128B
            int c = tid + i * 128, r = c >> 3, sg = c & 7;
            cp_async16(&Abuf[r * 72 + sg * 8], A + (size_t)(brow + r) * 1024 + k0 + sg * 8);
        }
#pragma unroll
        for (int i = 0; i < 8; i++) {          // B: 128 rows x 128B
            int c = tid + i * 128, r = c >> 3, sg = c & 7;
            cp_async16(&Bbuf[r * 72 + sg * 8], Bw + (size_t)(bcol + r) * 1024 + k0 + sg * 8);
        }
        CP_COMMIT();
    };

    float acc[4][8][4];
#pragma unroll
    for (int mi = 0; mi < 4; mi++)
#pragma unroll
        for (int ni = 0; ni < 8; ni++)
#pragma unroll
            for (int r = 0; r < 4; r++) acc[mi][ni][r] = 0.f;

    const int NIT = 1024 / 64;   // 16
    fill(0, 0);
    fill(64, 1);

    for (int it = 0; it < NIT; ++it) {
        if (it == NIT - 1) CP_WAIT(0); else CP_WAIT(1);
        __syncthreads();
        if (it + 2 < NIT) fill((it + 2) * 64, (it + 2) % 3);

        const int st = it % 3;
        const uint32_t aS = sbase + st * G_STG_H * 2;
        const uint32_t bS = aS + G_ROWS * 72 * 2;

#pragma unroll
        for (int ks = 0; ks < 4; ++ks) {
            uint32_t af[4][4], bf[8][2];
#pragma unroll
            for (int mi = 0; mi < 4; mi++)
                ldsm_x4(af[mi][0], af[mi][1], af[mi][2], af[mi][3],
                        aS + (wm + mi * 16) * 144 + ks * 32 + a_off);
#pragma unroll
            for (int nj = 0; nj < 8; nj += 2)
                ldsm_x4(bf[nj][0], bf[nj][1], bf[nj + 1][0], bf[nj + 1][1],
                        bS + (wn + nj * 8) * 144 + ks * 32 + b_off);
#pragma unroll
            for (int mi = 0; mi < 4; mi++)
#pragma unroll
                for (int ni = 0; ni < 8; ni++)
                    MMA_F16(acc[mi][ni], af[mi], bf[ni][0], bf[ni][1]);
        }
    }
    __syncthreads();

    // epilogue
#pragma unroll
    for (int mi = 0; mi < 4; mi++) {
#pragma unroll
        for (int ni = 0; ni < 8; ni++) {
            int gr = brow + wm + mi * 16 + lg;
            int gc = bcol + wn + ni * 8 + lt * 2;
            float bx = bias[gc], by = bias[gc + 1];
            float2 v0 = make_float2(acc[mi][ni][0] + bx, acc[mi][ni][1] + by);
            float2 v1 = make_float2(acc[mi][ni][2] + bx, acc[mi][ni][3] + by);
            if (MODE == 0) {
                *(float2*)&C[(size_t)gr * N + gc]       = v0;
                *(float2*)&C[(size_t)(gr + 8) * N + gc] = v1;
            } else {
                int which = gc >> 10;
                int hh    = (gc >> 6) & 15;
                int d     = gc & 63;
#pragma unroll
                for (int rr = 0; rr < 2; rr++) {
                    int row = gr + rr * 8;
                    int b   = row >> 11;
                    int s   = row & 2047;
                    int bh  = b * NH + hh;
                    float2 v = rr ? v1 : v0;
                    if (which == 0) {
                        *(uint32_t*)&g_q[((size_t)bh * Sq + s) * HD + d] =
                            pack_h2(v.x * 0.125f, v.y * 0.125f);
                    } else if (which == 1) {
                        *(uint32_t*)&g_k[((size_t)bh * Sq + s) * HD + d] =
                            pack_h2(v.x, v.y);
                    } else {
                        g_vT[((size_t)bh * HD + d)     * Sq + s] = __float2half_rn(v.x);
                        g_vT[((size_t)bh * HD + d + 1) * Sq + s] = __float2half_rn(v.y);
                    }
                }
            }
        }
    }
}

// ---------------------------------------------------------------------------
// FP16 causal flash attention. BM=128 (8 warps x 16 rows), BN=64, HD=64.
// Q frags in regs; P stays in registers (QK D-frag == PV A-frag layout).
// K/V double-buffered, ldmatrix B-frags. Rows 36 words (144B, conflict-free).
// ---------------------------------------------------------------------------
#define AQ_W (128 * 36)
#define AK_W (64 * 36)
#define AT_WORDS (AQ_W + 4 * AK_W)   // 13824 words = 55296 B

__global__ __launch_bounds__(256)
void attn_h()
{
    extern __shared__ uint32_t sm[];
    uint32_t* Qs  = sm;
    uint32_t* Kb[2]  = { sm + AQ_W,            sm + AQ_W + 2 * AK_W };
    uint32_t* Vb[2]  = { sm + AQ_W + AK_W,     sm + AQ_W + 3 * AK_W };

    const int tid  = threadIdx.x;
    const int lane = tid & 31;
    const int warp = tid >> 5;
    const int lg = lane >> 2;
    const int lt = lane & 3;
    const int qt = 15 - blockIdx.x;     // heavy tiles first
    const int bh = blockIdx.y;
    const int q0 = qt * 128;
    const int wm = warp * 16;

    const uint32_t a_off = (uint32_t)((lane & 15) * 144 + (lane >> 4) * 16);
    const uint32_t b_off = (uint32_t)((((lane >> 4) * 8) + (lane & 7)) * 144
                                      + ((lane >> 3) & 1) * 16);

    const uint32_t qs_a = (uint32_t)__cvta_generic_to_shared(Qs);
    const uint32_t kb_a[2] = { (uint32_t)__cvta_generic_to_shared(Kb[0]),
                               (uint32_t)__cvta_generic_to_shared(Kb[1]) };
    const uint32_t vb_a[2] = { (uint32_t)__cvta_generic_to_shared(Vb[0]),
                               (uint32_t)__cvta_generic_to_shared(Vb[1]) };

    // Q load
    const __half* q_ptr = g_q + ((size_t)bh * Sq + q0) * HD;
#pragma unroll
    for (int i = 0; i < 4; i++) {
        int id = tid + i * 256;
        int row = id >> 3, seg = id & 7;
        cp_async16((char*)&Qs[row * 36] + seg * 16, q_ptr + (size_t)row * HD + seg * 8);
    }
    CP_COMMIT();

    auto load_kv = [&](int kt, int b) {
        const __half* k_ptr = g_k  + ((size_t)bh * Sq + kt * 64) * HD;
        const __half* v_ptr = g_vT + (size_t)bh * HD * Sq + kt * 64;
#pragma unroll
        for (int i = 0; i < 2; i++) {
            int id = tid + i * 256;
            int row = id >> 3, seg = id & 7;
            cp_async16((char*)&Kb[b][row * 36] + seg * 16, k_ptr + (size_t)row * HD + seg * 8);
            cp_async16((char*)&Vb[b][row * 36] + seg * 16, v_ptr + (size_t)row * Sq + seg * 8);
        }
        CP_COMMIT();
    };
    load_kv(0, 0);

    CP_WAIT(1);
    __syncthreads();

    // Q fragments via ldmatrix (warp-private rows)
    uint32_t qf[4][4];
#pragma unroll
    for (int ks = 0; ks < 4; ks++)
        ldsm_x4(qf[ks][0], qf[ks][1], qf[ks][2], qf[ks][3],
                qs_a + wm * 144 + ks * 32 + a_off);

    float m_lo = -1e30f, m_hi = -1e30f, l_lo = 0.f, l_hi = 0.f;
    float o[8][4];
#pragma unroll
    for (int ni = 0; ni < 8; ni++)
#pragma unroll
        for (int c = 0; c < 4; c++) o[ni][c] = 0.f;

    const int row_lo = q0 + wm + lg;
    const int row_hi = row_lo + 8;
    const int nkt = 2 * qt + 2;

    for (int kt = 0; kt < nkt; kt++) {
        const int p = kt & 1;
        CP_WAIT(0);
        __syncthreads();
        if (kt + 1 < nkt) load_kv(kt + 1, p ^ 1);

        // S = Q @ K^T
        float s[8][4];
#pragma unroll
        for (int ni = 0; ni < 8; ni++)
#pragma unroll
            for (int c = 0; c < 4; c++) s[ni][c] = 0.f;

#pragma unroll
        for (int ks = 0; ks < 4; ks++) {
            uint32_t bf[8][2];
#pragma unroll
            for (int nj = 0; nj < 8; nj += 2)
                ldsm_x4(bf[nj][0], bf[nj][1], bf[nj + 1][0], bf[nj + 1][1],
                        kb_a[p] + (nj * 8) * 144 + ks * 32 + b_off);
#pragma unroll
            for (int ni = 0; ni < 8; ni++)
                MMA_F16(s[ni], qf[ks], bf[ni][0], bf[ni][1]);
        }

        if (kt >= 2 * qt) {
            const int colb = kt * 64;
#pragma unroll
            for (int ni = 0; ni < 8; ni++) {
                int c0 = colb + ni * 8 + lt * 2;
                if (c0 > row_lo)     s[ni][0] = -1e30f;
                if (c0 + 1 > row_lo) s[ni][1] = -1e30f;
                if (c0 > row_hi)     s[ni][2] = -1e30f;
                if (c0 + 1 > row_hi) s[ni][3] = -1e30f;
            }
        }

        // online softmax (reg stats, quad reduce)
        float rx_lo = -1e30f, rx_hi = -1e30f;
#pragma unroll
        for (int ni = 0; ni < 8; ni++) {
            rx_lo = fmaxf(rx_lo, fmaxf(s[ni][0], s[ni][1]));
            rx_hi = fmaxf(rx_hi, fmaxf(s[ni][2], s[ni][3]));
        }
        rx_lo = fmaxf(rx_lo, __shfl_xor_sync(0xffffffffu, rx_lo, 1));
        rx_lo = fmaxf(rx_lo, __shfl_xor_sync(0xffffffffu, rx_lo, 2));
        rx_hi = fmaxf(rx_hi, __shfl_xor_sync(0xffffffffu, rx_hi, 1));
        rx_hi = fmaxf(rx_hi, __shfl_xor_sync(0xffffffffu, rx_hi, 2));

        float mn_lo = fmaxf(m_lo, rx_lo);
        float mn_hi = fmaxf(m_hi, rx_hi);
        float al_lo = __expf(m_lo - mn_lo);
        float al_hi = __expf(m_hi - mn_hi);
        m_lo = mn_lo; m_hi = mn_hi;

        float rs_lo = 0.f, rs_hi = 0.f;
#pragma unroll
        for (int ni = 0; ni < 8; ni++) {
            s[ni][0] = __expf(s[ni][0] - mn_lo);
            s[ni][1] = __expf(s[ni][1] - mn_lo);
            s[ni][2] = __expf(s[ni][2] - mn_hi);
            s[ni][3] = __expf(s[ni][3] - mn_hi);
            rs_lo += s[ni][0] + s[ni][1];
            rs_hi += s[ni][2] + s[ni][3];
        }
        rs_lo += __shfl_xor_sync(0xffffffffu, rs_lo, 1);
        rs_lo += __shfl_xor_sync(0xffffffffu, rs_lo, 2);
        rs_hi += __shfl_xor_sync(0xffffffffu, rs_hi, 1);
        rs_hi += __shfl_xor_sync(0xffffffffu, rs_hi, 2);
        l_lo = l_lo * al_lo + rs_lo;
        l_hi = l_hi * al_hi + rs_hi;

#pragma unroll
        for (int ni = 0; ni < 8; ni++) {
            o[ni][0] *= al_lo; o[ni][1] *= al_lo;
            o[ni][2] *= al_hi; o[ni][3] *= al_hi;
        }

        // O += P @ V: P A-frags directly from s registers
#pragma unroll
        for (int ks = 0; ks < 4; ks++) {
            uint32_t pf[4];
            pf[0] = pack_h2(s[2 * ks][0],     s[2 * ks][1]);
            pf[1] = pack_h2(s[2 * ks][2],     s[2 * ks][3]);
            pf[2] = pack_h2(s[2 * ks + 1][0], s[2 * ks + 1][1]);
            pf[3] = pack_h2(s[2 * ks + 1][2], s[2 * ks + 1][3]);
            uint32_t bf[8][2];
#pragma unroll
            for (int nj = 0; nj < 8; nj += 2)
                ldsm_x4(bf[nj][0], bf[nj][1], bf[nj + 1][0], bf[nj + 1][1],
                        vb_a[p] + (nj * 8) * 144 + ks * 32 + b_off);
#pragma unroll
            for (int ni = 0; ni < 8; ni++)
                MMA_F16(o[ni], pf, bf[ni][0], bf[ni][1]);
        }
    }

    // epilogue: normalize, write ctx as half
    const int b = bh >> 4;
    const int h = bh & 15;
    const float inv_lo = 1.f / l_lo;
    const float inv_hi = 1.f / l_hi;
#pragma unroll
    for (int ni = 0; ni < 8; ni++) {
        int d = ni * 8 + lt * 2;
        size_t i0 = (((size_t)b * Sq + row_lo) << 10) + h * HD + d;
        size_t i1 = (((size_t)b * Sq + row_hi) << 10) + h * HD + d;
        *(uint32_t*)&g_ctx[i0] = pack_h2(o[ni][0] * inv_lo, o[ni][1] * inv_lo);
        *(uint32_t*)&g_ctx[i1] = pack_h2(o[ni][2] * inv_hi, o[ni][3] * inv_hi);
    }
}

// ---------------------------------------------------------------------------
// Launch
// ---------------------------------------------------------------------------
extern "C" void kernel_launch(void* const* d_in, const int* in_sizes, int n_in,
                              void* d_out, int out_size)
{
    const float* X       = (const float*)d_in[0];
    const float* W_qkv   = (const float*)d_in[2];
    const float* b_qkv   = (const float*)d_in[3];
    const float* W_dense = (const float*)d_in[4];
    const float* b_dense = (const float*)d_in[5];
    float* out = (float*)d_out;

    (void)in_sizes; (void)n_in; (void)out_size;

    __half *p_Xh, *p_Wqt, *p_Wdt, *p_ctx;
    cudaGetSymbolAddress((void**)&p_Xh,  g_Xh);
    cudaGetSymbolAddress((void**)&p_Wqt, g_Wqt);
    cudaGetSymbolAddress((void**)&p_Wdt, g_Wdt);
    cudaGetSymbolAddress((void**)&p_ctx, g_ctx);

    cudaFuncSetAttribute(gemm_h<1>, cudaFuncAttributeMaxDynamicSharedMemorySize, G_SMEM);
    cudaFuncSetAttribute(gemm_h<0>, cudaFuncAttributeMaxDynamicSharedMemorySize, G_SMEM);
    cudaFuncSetAttribute(attn_h, cudaFuncAttributeMaxDynamicSharedMemorySize, AT_WORDS * 4);

    // 0. prep: X -> half; W -> W^T half
    conv_h<<<(M1 * Hd / 4 + 255) / 256, 256>>>((const float4*)X, (uint2*)p_Xh, M1 * Hd / 4);
    transp_h<<<dim3(3 * Hd / 32, Hd / 32), dim3(32, 8)>>>(W_qkv, p_Wqt, Hd, 3 * Hd);
    transp_h<<<dim3(Hd / 32, Hd / 32), dim3(32, 8)>>>(W_dense, p_Wdt, Hd, Hd);

    // 1. QKV projection -> g_q (1/8 scaled), g_k, g_vT
    gemm_h<1><<<dim3(3 * Hd / 128, M1 / 128), 128, G_SMEM>>>(p_Xh, p_Wqt, b_qkv, nullptr, 3 * Hd);

    // 2. fp16 causal flash attention -> g_ctx (half)
    attn_h<<<dim3(16, BH), 256, AT_WORDS * 4>>>();

    // 3. output projection -> fp32 out
    gemm_h<0><<<dim3(Hd / 128, M1 / 128), 128, G_SMEM>>>(p_ctx, p_Wdt, b_dense, out, Hd);
}

// round 11
// speedup vs baseline: 2.5560x; 1.0571x over previous
#include <cuda_runtime.h>
#include <cuda_fp16.h>
#include <cstdint>

// Problem constants
#define Bsz 4
#define Sq  2048
#define Hd  1024
#define NH  16
#define HD  64
#define BH  (Bsz*NH)          // 64
#define M1  (Bsz*Sq)          // 8192
#define QKV_STRIDE ((size_t)BH*Sq*HD) // 8388608 halves per tensor

// Scratch (__device__ globals)
__device__ __half g_q  [QKV_STRIDE];            // [BH][S][HD], pre-scaled 1/8
__device__ __half g_k  [QKV_STRIDE];            // [BH][S][HD]
__device__ __half g_vT [QKV_STRIDE];            // [BH][HD][S]  (transposed)
__device__ __half g_ctx[(size_t)M1 * Hd];       // [B][S][H]
__device__ __half g_Xh [(size_t)M1 * Hd];       // X as half
__device__ __half g_Wqt[(size_t)3 * Hd * Hd];   // W_qkv^T  [3072][1024]
__device__ __half g_Wdt[(size_t)Hd * Hd];       // W_dense^T [1024][1024]

// ---------------------------------------------------------------------------
// Helpers
// ---------------------------------------------------------------------------
__device__ __forceinline__ uint32_t pack_h2(float a, float b) {
    __half2 h = __floats2half2_rn(a, b);
    return *(uint32_t*)&h;
}
__device__ __forceinline__ void cp_async16(void* smem_dst, const void* gmem_src) {
    uint32_t s = (uint32_t)__cvta_generic_to_shared(smem_dst);
    asm volatile("cp.async.cg.shared.global [%0], [%1], 16;\n" :: "r"(s), "l"(gmem_src));
}
#define CP_COMMIT() asm volatile("cp.async.commit_group;\n")
#define CP_WAIT(n)  asm volatile("cp.async.wait_group %0;\n" :: "n"(n))

__device__ __forceinline__ void ldsm_x4(uint32_t& r0, uint32_t& r1,
                                        uint32_t& r2, uint32_t& r3, uint32_t saddr) {
    asm volatile("ldmatrix.sync.aligned.m8n8.x4.shared.b16 {%0,%1,%2,%3}, [%4];"
                 : "=r"(r0), "=r"(r1), "=r"(r2), "=r"(r3) : "r"(saddr));
}

// fp16 mma, fp32 accum. A row-major (4 regs), B col-major (2 regs).
#define MMA_F16(acc, a, b0, b1)                                                \
    asm volatile(                                                              \
        "mma.sync.aligned.m16n8k16.row.col.f32.f16.f16.f32 "                   \
        "{%0,%1,%2,%3}, {%4,%5,%6,%7}, {%8,%9}, {%0,%1,%2,%3};\n"              \
        : "+f"((acc)[0]), "+f"((acc)[1]), "+f"((acc)[2]), "+f"((acc)[3])       \
        : "r"((a)[0]), "r"((a)[1]), "r"((a)[2]), "r"((a)[3]),                  \
          "r"(b0), "r"(b1))

// ---------------------------------------------------------------------------
// Prep: X fp32 -> half;  W fp32 [R][C] -> W^T half [C][R]
// ---------------------------------------------------------------------------
__global__ void conv_h(const float4* __restrict__ src, uint2* __restrict__ dst, int n4) {
    int i = blockIdx.x * blockDim.x + threadIdx.x;
    if (i < n4) {
        float4 v = src[i];
        dst[i] = make_uint2(pack_h2(v.x, v.y), pack_h2(v.z, v.w));
    }
}
__global__ void transp_h(const float* __restrict__ src, __half* __restrict__ dst,
                         int R, int C) {
    __shared__ __half t[32][33];
    int c0 = blockIdx.x * 32, r0 = blockIdx.y * 32;
    int tx = threadIdx.x, ty = threadIdx.y;   // 32 x 8
#pragma unroll
    for (int i = 0; i < 32; i += 8)
        t[ty + i][tx] = __float2half_rn(src[(size_t)(r0 + ty + i) * C + c0 + tx]);
    __syncthreads();
#pragma unroll
    for (int i = 0; i < 32; i += 8)
        dst[(size_t)(c0 + ty + i) * R + r0 + tx] = t[tx][ty + i];
}

// ---------------------------------------------------------------------------
// FP16 GEMM: C[M,N] = A[M,1024] @ Bw^T + bias.
// Block tile 128x128, 4 warps (2x2), warp tile 64x64. K-chunk 64,
// 2-stage cp.async ring, ONE sync per iter, 3 CTAs/SM target.
// Smem rows 72 halves (144B stride; LDSM conflict-free).
// MODE 0: fp32 row-major C.  MODE 1: scatter to g_q(1/8)/g_k/g_vT.
// ---------------------------------------------------------------------------
#define G_ROWS 128
#define G_STG_H (2 * G_ROWS * 72)            // 18432 halves per stage (A+B)
#define G_SMEM  (2 * G_STG_H * 2)            // 73728 bytes

template<int MODE>
__global__ __launch_bounds__(128, 3)
void gemm_h(const __half* __restrict__ A, const __half* __restrict__ Bw,
            const float* __restrict__ bias, float* __restrict__ C, int N)
{
    extern __shared__ __half gsm[];

    const int tid  = threadIdx.x;
    const int lane = tid & 31;
    const int warp = tid >> 5;
    const int wm   = (warp >> 1) * 64;    // 0 or 64
    const int wn   = (warp & 1) * 64;     // 0 or 64
    const int brow = blockIdx.y * 128;
    const int bcol = blockIdx.x * 128;
    const int lg = lane >> 2;
    const int lt = lane & 3;

    // ldmatrix per-lane byte offsets (144B row stride)
    const uint32_t a_off = (uint32_t)((lane & 15) * 144 + (lane >> 4) * 16);
    const uint32_t b_off = (uint32_t)((((lane >> 4) * 8) + (lane & 7)) * 144
                                      + ((lane >> 3) & 1) * 16);

    const uint32_t sbase = (uint32_t)__cvta_generic_to_shared(gsm);

    // fill stage st with K-chunk [k0, k0+64)
    auto fill = [&](int k0, int st) {
        __half* Abuf = gsm + st * G_STG_H;
        __half* Bbuf = Abuf + G_ROWS * 72;
        const int r = tid >> 3, sg = tid & 7;      // 16 rows per pass
#pragma unroll
        for (int i = 0; i < 8; i++)                // A: 128 rows x 128B
            cp_async16(&Abuf[(r + i * 16) * 72 + sg * 8],
                       A + (size_t)(brow + r + i * 16) * 1024 + k0 + sg * 8);
#pragma unroll
        for (int i = 0; i < 8; i++)                // B: 128 rows x 128B
            cp_async16(&Bbuf[(r + i * 16) * 72 + sg * 8],
                       Bw + (size_t)(bcol + r + i * 16) * 1024 + k0 + sg * 8);
        CP_COMMIT();
    };

    float acc[4][8][4];
#pragma unroll
    for (int mi = 0; mi < 4; mi++)
#pragma unroll
        for (int ni = 0; ni < 8; ni++)
#pragma unroll
            for (int r = 0; r < 4; r++) acc[mi][ni][r] = 0.f;

    const int NIT = 1024 / 64;   // 16
    fill(0, 0);

    for (int it = 0; it < NIT; ++it) {
        CP_WAIT(0);              // stage it landed
        __syncthreads();         // all warps done computing it-1 (same buffer as it+1)
        if (it + 1 < NIT) fill((it + 1) * 64, (it + 1) & 1);

        const uint32_t aS = sbase + (it & 1) * G_STG_H * 2;
        const uint32_t bS = aS + G_ROWS * 72 * 2;

#pragma unroll
        for (int ks = 0; ks < 4; ++ks) {
            uint32_t af[4][4];
#pragma unroll
            for (int mi = 0; mi < 4; mi++)
                ldsm_x4(af[mi][0], af[mi][1], af[mi][2], af[mi][3],
                        aS + (wm + mi * 16) * 144 + ks * 32 + a_off);
#pragma unroll
            for (int nj = 0; nj < 8; nj += 2) {
                uint32_t b00, b01, b10, b11;
                ldsm_x4(b00, b01, b10, b11,
                        bS + (wn + nj * 8) * 144 + ks * 32 + b_off);
#pragma unroll
                for (int mi = 0; mi < 4; mi++) {
                    MMA_F16(acc[mi][nj],     af[mi], b00, b01);
                    MMA_F16(acc[mi][nj + 1], af[mi], b10, b11);
                }
            }
        }
    }

    // epilogue
#pragma unroll
    for (int mi = 0; mi < 4; mi++) {
#pragma unroll
        for (int ni = 0; ni < 8; ni++) {
            int gr = brow + wm + mi * 16 + lg;
            int gc = bcol + wn + ni * 8 + lt * 2;
            float bx = bias[gc], by = bias[gc + 1];
            float2 v0 = make_float2(acc[mi][ni][0] + bx, acc[mi][ni][1] + by);
            float2 v1 = make_float2(acc[mi][ni][2] + bx, acc[mi][ni][3] + by);
            if (MODE == 0) {
                *(float2*)&C[(size_t)gr * N + gc]       = v0;
                *(float2*)&C[(size_t)(gr + 8) * N + gc] = v1;
            } else {
                int which = gc >> 10;
                int hh    = (gc >> 6) & 15;
                int d     = gc & 63;
#pragma unroll
                for (int rr = 0; rr < 2; rr++) {
                    int row = gr + rr * 8;
                    int b   = row >> 11;
                    int s   = row & 2047;
                    int bh  = b * NH + hh;
                    float2 v = rr ? v1 : v0;
                    if (which == 0) {
                        *(uint32_t*)&g_q[((size_t)bh * Sq + s) * HD + d] =
                            pack_h2(v.x * 0.125f, v.y * 0.125f);
                    } else if (which == 1) {
                        *(uint32_t*)&g_k[((size_t)bh * Sq + s) * HD + d] =
                            pack_h2(v.x, v.y);
                    } else {
                        g_vT[((size_t)bh * HD + d)     * Sq + s] = __float2half_rn(v.x);
                        g_vT[((size_t)bh * HD + d + 1) * Sq + s] = __float2half_rn(v.y);
                    }
                }
            }
        }
    }
}

// ---------------------------------------------------------------------------
// FP16 causal flash attention. BM=128 (8 warps x 16 rows), BN=64, HD=64.
// Q frags in regs; P stays in registers (QK D-frag == PV A-frag layout).
// K/V double-buffered, ldmatrix B-frags interleaved with MMAs (low reg
// pressure -> 2 CTAs/SM). Rows 36 words (144B, conflict-free).
// ---------------------------------------------------------------------------
#define AQ_W (128 * 36)
#define AK_W (64 * 36)
#define AT_WORDS (AQ_W + 4 * AK_W)   // 13824 words = 55296 B

__global__ __launch_bounds__(256, 2)
void attn_h()
{
    extern __shared__ uint32_t sm[];
    uint32_t* Qs  = sm;
    uint32_t* Kb[2]  = { sm + AQ_W,            sm + AQ_W + 2 * AK_W };
    uint32_t* Vb[2]  = { sm + AQ_W + AK_W,     sm + AQ_W + 3 * AK_W };

    const int tid  = threadIdx.x;
    const int lane = tid & 31;
    const int warp = tid >> 5;
    const int lg = lane >> 2;
    const int lt = lane & 3;
    const int qt = 15 - blockIdx.x;     // heavy tiles first
    const int bh = blockIdx.y;
    const int q0 = qt * 128;
    const int wm = warp * 16;

    const uint32_t a_off = (uint32_t)((lane & 15) * 144 + (lane >> 4) * 16);
    const uint32_t b_off = (uint32_t)((((lane >> 4) * 8) + (lane & 7)) * 144
                                      + ((lane >> 3) & 1) * 16);

    const uint32_t qs_a = (uint32_t)__cvta_generic_to_shared(Qs);
    const uint32_t kb_a[2] = { (uint32_t)__cvta_generic_to_shared(Kb[0]),
                               (uint32_t)__cvta_generic_to_shared(Kb[1]) };
    const uint32_t vb_a[2] = { (uint32_t)__cvta_generic_to_shared(Vb[0]),
                               (uint32_t)__cvta_generic_to_shared(Vb[1]) };

    // Q load
    const __half* q_ptr = g_q + ((size_t)bh * Sq + q0) * HD;
#pragma unroll
    for (int i = 0; i < 4; i++) {
        int id = tid + i * 256;
        int row = id >> 3, seg = id & 7;
        cp_async16((char*)&Qs[row * 36] + seg * 16, q_ptr + (size_t)row * HD + seg * 8);
    }
    CP_COMMIT();

    auto load_kv = [&](int kt, int b) {
        const __half* k_ptr = g_k  + ((size_t)bh * Sq + kt * 64) * HD;
        const __half* v_ptr = g_vT + (size_t)bh * HD * Sq + kt * 64;
#pragma unroll
        for (int i = 0; i < 2; i++) {
            int id = tid + i * 256;
            int row = id >> 3, seg = id & 7;
            cp_async16((char*)&Kb[b][row * 36] + seg * 16, k_ptr + (size_t)row * HD + seg * 8);
            cp_async16((char*)&Vb[b][row * 36] + seg * 16, v_ptr + (size_t)row * Sq + seg * 8);
        }
        CP_COMMIT();
    };
    load_kv(0, 0);

    CP_WAIT(1);
    __syncthreads();

    // Q fragments via ldmatrix (warp-private rows)
    uint32_t qf[4][4];
#pragma unroll
    for (int ks = 0; ks < 4; ks++)
        ldsm_x4(qf[ks][0], qf[ks][1], qf[ks][2], qf[ks][3],
                qs_a + wm * 144 + ks * 32 + a_off);

    float m_lo = -1e30f, m_hi = -1e30f, l_lo = 0.f, l_hi = 0.f;
    float o[8][4];
#pragma unroll
    for (int ni = 0; ni < 8; ni++)
#pragma unroll
        for (int c = 0; c < 4; c++) o[ni][c] = 0.f;

    const int row_lo = q0 + wm + lg;
    const int row_hi = row_lo + 8;
    const int nkt = 2 * qt + 2;

    for (int kt = 0; kt < nkt; kt++) {
        const int p = kt & 1;
        CP_WAIT(0);
        __syncthreads();
        if (kt + 1 < nkt) load_kv(kt + 1, p ^ 1);

        // S = Q @ K^T  (LDSM pair interleaved with MMAs: low live-reg count)
        float s[8][4];
#pragma unroll
        for (int ni = 0; ni < 8; ni++)
#pragma unroll
            for (int c = 0; c < 4; c++) s[ni][c] = 0.f;

#pragma unroll
        for (int ks = 0; ks < 4; ks++) {
#pragma unroll
            for (int nj = 0; nj < 8; nj += 2) {
                uint32_t b00, b01, b10, b11;
                ldsm_x4(b00, b01, b10, b11,
                        kb_a[p] + (nj * 8) * 144 + ks * 32 + b_off);
                MMA_F16(s[nj],     qf[ks], b00, b01);
                MMA_F16(s[nj + 1], qf[ks], b10, b11);
            }
        }

        if (kt >= 2 * qt) {
            const int colb = kt * 64;
#pragma unroll
            for (int ni = 0; ni < 8; ni++) {
                int c0 = colb + ni * 8 + lt * 2;
                if (c0 > row_lo)     s[ni][0] = -1e30f;
                if (c0 + 1 > row_lo) s[ni][1] = -1e30f;
                if (c0 > row_hi)     s[ni][2] = -1e30f;
                if (c0 + 1 > row_hi) s[ni][3] = -1e30f;
            }
        }

        // online softmax (reg stats, quad reduce)
        float rx_lo = -1e30f, rx_hi = -1e30f;
#pragma unroll
        for (int ni = 0; ni < 8; ni++) {
            rx_lo = fmaxf(rx_lo, fmaxf(s[ni][0], s[ni][1]));
            rx_hi = fmaxf(rx_hi, fmaxf(s[ni][2], s[ni][3]));
        }
        rx_lo = fmaxf(rx_lo, __shfl_xor_sync(0xffffffffu, rx_lo, 1));
        rx_lo = fmaxf(rx_lo, __shfl_xor_sync(0xffffffffu, rx_lo, 2));
        rx_hi = fmaxf(rx_hi, __shfl_xor_sync(0xffffffffu, rx_hi, 1));
        rx_hi = fmaxf(rx_hi, __shfl_xor_sync(0xffffffffu, rx_hi, 2));

        float mn_lo = fmaxf(m_lo, rx_lo);
        float mn_hi = fmaxf(m_hi, rx_hi);
        float al_lo = __expf(m_lo - mn_lo);
        float al_hi = __expf(m_hi - mn_hi);
        m_lo = mn_lo; m_hi = mn_hi;

        float rs_lo = 0.f, rs_hi = 0.f;
#pragma unroll
        for (int ni = 0; ni < 8; ni++) {
            s[ni][0] = __expf(s[ni][0] - mn_lo);
            s[ni][1] = __expf(s[ni][1] - mn_lo);
            s[ni][2] = __expf(s[ni][2] - mn_hi);
            s[ni][3] = __expf(s[ni][3] - mn_hi);
            rs_lo += s[ni][0] + s[ni][1];
            rs_hi += s[ni][2] + s[ni][3];
        }
        rs_lo += __shfl_xor_sync(0xffffffffu, rs_lo, 1);
        rs_lo += __shfl_xor_sync(0xffffffffu, rs_lo, 2);
        rs_hi += __shfl_xor_sync(0xffffffffu, rs_hi, 1);
        rs_hi += __shfl_xor_sync(0xffffffffu, rs_hi, 2);
        l_lo = l_lo * al_lo + rs_lo;
        l_hi = l_hi * al_hi + rs_hi;

#pragma unroll
        for (int ni = 0; ni < 8; ni++) {
            o[ni][0] *= al_lo; o[ni][1] *= al_lo;
            o[ni][2] *= al_hi; o[ni][3] *= al_hi;
        }

        // O += P @ V: P A-frags directly from s registers, LDSM interleaved
#pragma unroll
        for (int ks = 0; ks < 4; ks++) {
            uint32_t pf[4];
            pf[0] = pack_h2(s[2 * ks][0],     s[2 * ks][1]);
            pf[1] = pack_h2(s[2 * ks][2],     s[2 * ks][3]);
            pf[2] = pack_h2(s[2 * ks + 1][0], s[2 * ks + 1][1]);
            pf[3] = pack_h2(s[2 * ks + 1][2], s[2 * ks + 1][3]);
#pragma unroll
            for (int nj = 0; nj < 8; nj += 2) {
                uint32_t b00, b01, b10, b11;
                ldsm_x4(b00, b01, b10, b11,
                        vb_a[p] + (nj * 8) * 144 + ks * 32 + b_off);
                MMA_F16(o[nj],     pf, b00, b01);
                MMA_F16(o[nj + 1], pf, b10, b11);
            }
        }
    }

    // epilogue: normalize, write ctx as half
    const int b = bh >> 4;
    const int h = bh & 15;
    const float inv_lo = 1.f / l_lo;
    const float inv_hi = 1.f / l_hi;
#pragma unroll
    for (int ni = 0; ni < 8; ni++) {
        int d = ni * 8 + lt * 2;
        size_t i0 = (((size_t)b * Sq + row_lo) << 10) + h * HD + d;
        size_t i1 = (((size_t)b * Sq + row_hi) << 10) + h * HD + d;
        *(uint32_t*)&g_ctx[i0] = pack_h2(o[ni][0] * inv_lo, o[ni][1] * inv_lo);
        *(uint32_t*)&g_ctx[i1] = pack_h2(o[ni][2] * inv_hi, o[ni][3] * inv_hi);
    }
}

// ---------------------------------------------------------------------------
// Launch
// ---------------------------------------------------------------------------
extern "C" void kernel_launch(void* const* d_in, const int* in_sizes, int n_in,
                              void* d_out, int out_size)
{
    const float* X       = (const float*)d_in[0];
    const float* W_qkv   = (const float*)d_in[2];
    const float* b_qkv   = (const float*)d_in[3];
    const float* W_dense = (const float*)d_in[4];
    const float* b_dense = (const float*)d_in[5];
    float* out = (float*)d_out;

    (void)in_sizes; (void)n_in; (void)out_size;

    __half *p_Xh, *p_Wqt, *p_Wdt, *p_ctx;
    cudaGetSymbolAddress((void**)&p_Xh,  g_Xh);
    cudaGetSymbolAddress((void**)&p_Wqt, g_Wqt);
    cudaGetSymbolAddress((void**)&p_Wdt, g_Wdt);
    cudaGetSymbolAddress((void**)&p_ctx, g_ctx);

    cudaFuncSetAttribute(gemm_h<1>, cudaFuncAttributeMaxDynamicSharedMemorySize, G_SMEM);
    cudaFuncSetAttribute(gemm_h<0>, cudaFuncAttributeMaxDynamicSharedMemorySize, G_SMEM);
    cudaFuncSetAttribute(attn_h, cudaFuncAttributeMaxDynamicSharedMemorySize, AT_WORDS * 4);

    // 0. prep: X -> half; W -> W^T half
    conv_h<<<(M1 * Hd / 4 + 255) / 256, 256>>>((const float4*)X, (uint2*)p_Xh, M1 * Hd / 4);
    transp_h<<<dim3(3 * Hd / 32, Hd / 32), dim3(32, 8)>>>(W_qkv, p_Wqt, Hd, 3 * Hd);
    transp_h<<<dim3(Hd / 32, Hd / 32), dim3(32, 8)>>>(W_dense, p_Wdt, Hd, Hd);

    // 1. QKV projection -> g_q (1/8 scaled), g_k, g_vT
    gemm_h<1><<<dim3(3 * Hd / 128, M1 / 128), 128, G_SMEM>>>(p_Xh, p_Wqt, b_qkv, nullptr, 3 * Hd);

    // 2. fp16 causal flash attention -> g_ctx (half)
    attn_h<<<dim3(16, BH), 256, AT_WORDS * 4>>>();

    // 3. output projection -> fp32 out
    gemm_h<0><<<dim3(Hd / 128, M1 / 128), 128, G_SMEM>>>(p_ctx, p_Wdt, b_dense, out, Hd);
}

// round 14
// speedup vs baseline: 2.6583x; 1.0400x over previous
#include <cuda_runtime.h>
#include <cuda_fp16.h>
#include <cstdint>

// Problem constants
#define Bsz 4
#define Sq  2048
#define Hd  1024
#define NH  16
#define HD  64
#define BH  (Bsz*NH)          // 64
#define M1  (Bsz*Sq)          // 8192
#define QKV_STRIDE ((size_t)BH*Sq*HD) // 8388608 halves per tensor

// Scratch (__device__ globals)
__device__ __half g_q  [QKV_STRIDE];            // [BH][S][HD], pre-scaled 0.125*log2e
__device__ __half g_k  [QKV_STRIDE];            // [BH][S][HD]
__device__ __half g_vT [QKV_STRIDE];            // [BH][HD][S]  (transposed)
__device__ __half g_ctx[(size_t)M1 * Hd];       // [B][S][H]
__device__ __half g_Xh [(size_t)M1 * Hd];       // X as half
__device__ __half g_Wqt[(size_t)3 * Hd * Hd];   // W_qkv^T  [3072][1024]
__device__ __half g_Wdt[(size_t)Hd * Hd];       // W_dense^T [1024][1024]

// ---------------------------------------------------------------------------
// Helpers
// ---------------------------------------------------------------------------
__device__ __forceinline__ uint32_t pack_h2(float a, float b) {
    __half2 h = __floats2half2_rn(a, b);
    return *(uint32_t*)&h;
}
__device__ __forceinline__ float ex2(float x) {
    float y;
    asm("ex2.approx.ftz.f32 %0, %1;" : "=f"(y) : "f"(x));
    return y;
}
__device__ __forceinline__ void cp_async16(void* smem_dst, const void* gmem_src) {
    uint32_t s = (uint32_t)__cvta_generic_to_shared(smem_dst);
    asm volatile("cp.async.cg.shared.global [%0], [%1], 16;\n" :: "r"(s), "l"(gmem_src));
}
#define CP_COMMIT() asm volatile("cp.async.commit_group;\n")
#define CP_WAIT(n)  asm volatile("cp.async.wait_group %0;\n" :: "n"(n))

__device__ __forceinline__ void ldsm_x4(uint32_t& r0, uint32_t& r1,
                                        uint32_t& r2, uint32_t& r3, uint32_t saddr) {
    asm volatile("ldmatrix.sync.aligned.m8n8.x4.shared.b16 {%0,%1,%2,%3}, [%4];"
                 : "=r"(r0), "=r"(r1), "=r"(r2), "=r"(r3) : "r"(saddr));
}

// fp16 mma, fp32 accum. A row-major (4 regs), B col-major (2 regs).
#define MMA_F16(acc, a, b0, b1)                                                \
    asm volatile(                                                              \
        "mma.sync.aligned.m16n8k16.row.col.f32.f16.f16.f32 "                   \
        "{%0,%1,%2,%3}, {%4,%5,%6,%7}, {%8,%9}, {%0,%1,%2,%3};\n"              \
        : "+f"((acc)[0]), "+f"((acc)[1]), "+f"((acc)[2]), "+f"((acc)[3])       \
        : "r"((a)[0]), "r"((a)[1]), "r"((a)[2]), "r"((a)[3]),                  \
          "r"(b0), "r"(b1))

// ---------------------------------------------------------------------------
// Fused prep (single launch):
//   blocks [0, NB_CONV)               : X fp32 -> half
//   blocks [NB_CONV, +NB_TQ)          : W_qkv  [1024][3072] -> W_qkv^T half
//   blocks [NB_CONV+NB_TQ, +NB_TD)    : W_dense[1024][1024] -> W_dense^T half
// ---------------------------------------------------------------------------
#define NB_CONV (M1 * Hd / 4 / 256)          // 8192
#define NB_TQ   ((3 * Hd / 32) * (Hd / 32))  // 3072
#define NB_TD   ((Hd / 32) * (Hd / 32))      // 1024

__global__ __launch_bounds__(256)
void prep_all(const float4* __restrict__ X4, uint2* __restrict__ Xh4,
              const float* __restrict__ Wq, __half* __restrict__ Wqt,
              const float* __restrict__ Wd, __half* __restrict__ Wdt)
{
    const int b = blockIdx.x;
    const int tid = threadIdx.x;

    if (b < NB_CONV) {
        int i = b * 256 + tid;
        float4 v = X4[i];
        Xh4[i] = make_uint2(pack_h2(v.x, v.y), pack_h2(v.z, v.w));
        return;
    }
    // transpose section: src[R][C] -> dst[C][R]
    __shared__ __half t[32][33];
    const float* src;  __half* dst;  int R, C, tb;
    if (b < NB_CONV + NB_TQ) { tb = b - NB_CONV;         src = Wq; dst = Wqt; R = Hd; C = 3 * Hd; }
    else                     { tb = b - NB_CONV - NB_TQ; src = Wd; dst = Wdt; R = Hd; C = Hd; }
    const int nbx = C / 32;
    const int c0 = (tb % nbx) * 32, r0 = (tb / nbx) * 32;
    const int tx = tid & 31, ty = tid >> 5;   // 32 x 8
#pragma unroll
    for (int i = 0; i < 32; i += 8)
        t[ty + i][tx] = __float2half_rn(src[(size_t)(r0 + ty + i) * C + c0 + tx]);
    __syncthreads();
#pragma unroll
    for (int i = 0; i < 32; i += 8)
        dst[(size_t)(c0 + ty + i) * R + r0 + tx] = t[tx][ty + i];
}

// ---------------------------------------------------------------------------
// FP16 GEMM: C[M,N] = A[M,1024] @ Bw^T + bias.
// Block tile 128x128, 4 warps (2x2), warp tile 64x64. K-chunk 64,
// 2-stage cp.async ring, ONE sync per iter, 3 CTAs/SM.
// Smem rows 72 halves (144B stride; LDSM conflict-free).
// MODE 0: fp32 row-major C.  MODE 1: scatter to g_q(0.125*log2e)/g_k/g_vT.
// ---------------------------------------------------------------------------
#define G_ROWS 128
#define G_STG_H (2 * G_ROWS * 72)            // 18432 halves per stage (A+B)
#define G_SMEM  (2 * G_STG_H * 2)            // 73728 bytes
#define QSCALE  (0.125f * 1.4426950408889634f)

template<int MODE>
__global__ __launch_bounds__(128, 3)
void gemm_h(const __half* __restrict__ A, const __half* __restrict__ Bw,
            const float* __restrict__ bias, float* __restrict__ C, int N)
{
    extern __shared__ __half gsm[];

    const int tid  = threadIdx.x;
    const int lane = tid & 31;
    const int warp = tid >> 5;
    const int wm   = (warp >> 1) * 64;
    const int wn   = (warp & 1) * 64;
    const int brow = blockIdx.y * 128;
    const int bcol = blockIdx.x * 128;
    const int lg = lane >> 2;
    const int lt = lane & 3;

    const uint32_t a_off = (uint32_t)((lane & 15) * 144 + (lane >> 4) * 16);
    const uint32_t b_off = (uint32_t)((((lane >> 4) * 8) + (lane & 7)) * 144
                                      + ((lane >> 3) & 1) * 16);

    const uint32_t sbase = (uint32_t)__cvta_generic_to_shared(gsm);

    auto fill = [&](int k0, int st) {
        __half* Abuf = gsm + st * G_STG_H;
        __half* Bbuf = Abuf + G_ROWS * 72;
        const int r = tid >> 3, sg = tid & 7;
#pragma unroll
        for (int i = 0; i < 8; i++)
            cp_async16(&Abuf[(r + i * 16) * 72 + sg * 8],
                       A + (size_t)(brow + r + i * 16) * 1024 + k0 + sg * 8);
#pragma unroll
        for (int i = 0; i < 8; i++)
            cp_async16(&Bbuf[(r + i * 16) * 72 + sg * 8],
                       Bw + (size_t)(bcol + r + i * 16) * 1024 + k0 + sg * 8);
        CP_COMMIT();
    };

    float acc[4][8][4];
#pragma unroll
    for (int mi = 0; mi < 4; mi++)
#pragma unroll
        for (int ni = 0; ni < 8; ni++)
#pragma unroll
            for (int r = 0; r < 4; r++) acc[mi][ni][r] = 0.f;

    const int NIT = 1024 / 64;   // 16
    fill(0, 0);

    for (int it = 0; it < NIT; ++it) {
        CP_WAIT(0);
        __syncthreads();
        if (it + 1 < NIT) fill((it + 1) * 64, (it + 1) & 1);

        const uint32_t aS = sbase + (it & 1) * G_STG_H * 2;
        const uint32_t bS = aS + G_ROWS * 72 * 2;

#pragma unroll
        for (int ks = 0; ks < 4; ++ks) {
            uint32_t af[4][4];
#pragma unroll
            for (int mi = 0; mi < 4; mi++)
                ldsm_x4(af[mi][0], af[mi][1], af[mi][2], af[mi][3],
                        aS + (wm + mi * 16) * 144 + ks * 32 + a_off);
#pragma unroll
            for (int nj = 0; nj < 8; nj += 2) {
                uint32_t b00, b01, b10, b11;
                ldsm_x4(b00, b01, b10, b11,
                        bS + (wn + nj * 8) * 144 + ks * 32 + b_off);
#pragma unroll
                for (int mi = 0; mi < 4; mi++) {
                    MMA_F16(acc[mi][nj],     af[mi], b00, b01);
                    MMA_F16(acc[mi][nj + 1], af[mi], b10, b11);
                }
            }
        }
    }

    // epilogue
#pragma unroll
    for (int mi = 0; mi < 4; mi++) {
#pragma unroll
        for (int ni = 0; ni < 8; ni++) {
            int gr = brow + wm + mi * 16 + lg;
            int gc = bcol + wn + ni * 8 + lt * 2;
            float bx = bias[gc], by = bias[gc + 1];
            float2 v0 = make_float2(acc[mi][ni][0] + bx, acc[mi][ni][1] + by);
            float2 v1 = make_float2(acc[mi][ni][2] + bx, acc[mi][ni][3] + by);
            if (MODE == 0) {
                *(float2*)&C[(size_t)gr * N + gc]       = v0;
                *(float2*)&C[(size_t)(gr + 8) * N + gc] = v1;
            } else {
                int which = gc >> 10;
                int hh    = (gc >> 6) & 15;
                int d     = gc & 63;
#pragma unroll
                for (int rr = 0; rr < 2; rr++) {
                    int row = gr + rr * 8;
                    int b   = row >> 11;
                    int s   = row & 2047;
                    int bh  = b * NH + hh;
                    float2 v = rr ? v1 : v0;
                    if (which == 0) {
                        *(uint32_t*)&g_q[((size_t)bh * Sq + s) * HD + d] =
                            pack_h2(v.x * QSCALE, v.y * QSCALE);
                    } else if (which == 1) {
                        *(uint32_t*)&g_k[((size_t)bh * Sq + s) * HD + d] =
                            pack_h2(v.x, v.y);
                    } else {
                        g_vT[((size_t)bh * HD + d)     * Sq + s] = __float2half_rn(v.x);
                        g_vT[((size_t)bh * HD + d + 1) * Sq + s] = __float2half_rn(v.y);
                    }
                }
            }
        }
    }
}

// ---------------------------------------------------------------------------
// FP16 causal flash attention, log2-domain softmax (scale pre-folded into Q).
// Structure IDENTICAL to the R11 passing kernel: BM=128 (8 warps x 16 rows),
// BN=64, HD=64, double-buffered K/V, sync every tile, P in registers.
// Rows 36 words (144B, LDSM conflict-free).
// ---------------------------------------------------------------------------
#define AQ_W (128 * 36)
#define AK_W (64 * 36)
#define AT_WORDS (AQ_W + 4 * AK_W)   // 13824 words = 55296 B

__global__ __launch_bounds__(256, 2)
void attn_h()
{
    extern __shared__ uint32_t sm[];
    uint32_t* Qs  = sm;
    uint32_t* Kb[2]  = { sm + AQ_W,            sm + AQ_W + 2 * AK_W };
    uint32_t* Vb[2]  = { sm + AQ_W + AK_W,     sm + AQ_W + 3 * AK_W };

    const int tid  = threadIdx.x;
    const int lane = tid & 31;
    const int warp = tid >> 5;
    const int lg = lane >> 2;
    const int lt = lane & 3;
    const int qt = 15 - blockIdx.x;     // heavy tiles first
    const int bh = blockIdx.y;
    const int q0 = qt * 128;
    const int wm = warp * 16;

    const uint32_t a_off = (uint32_t)((lane & 15) * 144 + (lane >> 4) * 16);
    const uint32_t b_off = (uint32_t)((((lane >> 4) * 8) + (lane & 7)) * 144
                                      + ((lane >> 3) & 1) * 16);

    const uint32_t qs_a = (uint32_t)__cvta_generic_to_shared(Qs);
    const uint32_t kb_a[2] = { (uint32_t)__cvta_generic_to_shared(Kb[0]),
                               (uint32_t)__cvta_generic_to_shared(Kb[1]) };
    const uint32_t vb_a[2] = { (uint32_t)__cvta_generic_to_shared(Vb[0]),
                               (uint32_t)__cvta_generic_to_shared(Vb[1]) };

    // Q load
    const __half* q_ptr = g_q + ((size_t)bh * Sq + q0) * HD;
#pragma unroll
    for (int i = 0; i < 4; i++) {
        int id = tid + i * 256;
        int row = id >> 3, seg = id & 7;
        cp_async16((char*)&Qs[row * 36] + seg * 16, q_ptr + (size_t)row * HD + seg * 8);
    }
    CP_COMMIT();

    auto load_kv = [&](int kt, int b) {
        const __half* k_ptr = g_k  + ((size_t)bh * Sq + kt * 64) * HD;
        const __half* v_ptr = g_vT + (size_t)bh * HD * Sq + kt * 64;
#pragma unroll
        for (int i = 0; i < 2; i++) {
            int id = tid + i * 256;
            int row = id >> 3, seg = id & 7;
            cp_async16((char*)&Kb[b][row * 36] + seg * 16, k_ptr + (size_t)row * HD + seg * 8);
            cp_async16((char*)&Vb[b][row * 36] + seg * 16, v_ptr + (size_t)row * Sq + seg * 8);
        }
        CP_COMMIT();
    };
    load_kv(0, 0);

    CP_WAIT(1);
    __syncthreads();

    // Q fragments via ldmatrix (warp-private rows)
    uint32_t qf[4][4];
#pragma unroll
    for (int ks = 0; ks < 4; ks++)
        ldsm_x4(qf[ks][0], qf[ks][1], qf[ks][2], qf[ks][3],
                qs_a + wm * 144 + ks * 32 + a_off);

    float m_lo = -1e30f, m_hi = -1e30f, l_lo = 0.f, l_hi = 0.f;
    float o[8][4];
#pragma unroll
    for (int ni = 0; ni < 8; ni++)
#pragma unroll
        for (int c = 0; c < 4; c++) o[ni][c] = 0.f;

    const int row_lo = q0 + wm + lg;
    const int row_hi = row_lo + 8;
    const int nkt = 2 * qt + 2;

    for (int kt = 0; kt < nkt; kt++) {
        const int p = kt & 1;
        CP_WAIT(0);
        __syncthreads();
        if (kt + 1 < nkt) load_kv(kt + 1, p ^ 1);

        // S = Q @ K^T (log2 domain; scale folded into Q)
        float s[8][4];
#pragma unroll
        for (int ni = 0; ni < 8; ni++)
#pragma unroll
            for (int c = 0; c < 4; c++) s[ni][c] = 0.f;

#pragma unroll
        for (int ks = 0; ks < 4; ks++) {
#pragma unroll
            for (int nj = 0; nj < 8; nj += 2) {
                uint32_t b00, b01, b10, b11;
                ldsm_x4(b00, b01, b10, b11,
                        kb_a[p] + (nj * 8) * 144 + ks * 32 + b_off);
                MMA_F16(s[nj],     qf[ks], b00, b01);
                MMA_F16(s[nj + 1], qf[ks], b10, b11);
            }
        }

        if (kt >= 2 * qt) {
            const int colb = kt * 64;
#pragma unroll
            for (int ni = 0; ni < 8; ni++) {
                int c0 = colb + ni * 8 + lt * 2;
                if (c0 > row_lo)     s[ni][0] = -1e30f;
                if (c0 + 1 > row_lo) s[ni][1] = -1e30f;
                if (c0 > row_hi)     s[ni][2] = -1e30f;
                if (c0 + 1 > row_hi) s[ni][3] = -1e30f;
            }
        }

        // online softmax in log2 domain (reg stats, quad reduce)
        float rx_lo = -1e30f, rx_hi = -1e30f;
#pragma unroll
        for (int ni = 0; ni < 8; ni++) {
            rx_lo = fmaxf(rx_lo, fmaxf(s[ni][0], s[ni][1]));
            rx_hi = fmaxf(rx_hi, fmaxf(s[ni][2], s[ni][3]));
        }
        rx_lo = fmaxf(rx_lo, __shfl_xor_sync(0xffffffffu, rx_lo, 1));
        rx_lo = fmaxf(rx_lo, __shfl_xor_sync(0xffffffffu, rx_lo, 2));
        rx_hi = fmaxf(rx_hi, __shfl_xor_sync(0xffffffffu, rx_hi, 1));
        rx_hi = fmaxf(rx_hi, __shfl_xor_sync(0xffffffffu, rx_hi, 2));

        float mn_lo = fmaxf(m_lo, rx_lo);
        float mn_hi = fmaxf(m_hi, rx_hi);
        float al_lo = ex2(m_lo - mn_lo);
        float al_hi = ex2(m_hi - mn_hi);
        m_lo = mn_lo; m_hi = mn_hi;

        float rs_lo = 0.f, rs_hi = 0.f;
#pragma unroll
        for (int ni = 0; ni < 8; ni++) {
            s[ni][0] = ex2(s[ni][0] - mn_lo);
            s[ni][1] = ex2(s[ni][1] - mn_lo);
            s[ni][2] = ex2(s[ni][2] - mn_hi);
            s[ni][3] = ex2(s[ni][3] - mn_hi);
            rs_lo += s[ni][0] + s[ni][1];
            rs_hi += s[ni][2] + s[ni][3];
        }
        rs_lo += __shfl_xor_sync(0xffffffffu, rs_lo, 1);
        rs_lo += __shfl_xor_sync(0xffffffffu, rs_lo, 2);
        rs_hi += __shfl_xor_sync(0xffffffffu, rs_hi, 1);
        rs_hi += __shfl_xor_sync(0xffffffffu, rs_hi, 2);
        l_lo = l_lo * al_lo + rs_lo;
        l_hi = l_hi * al_hi + rs_hi;

#pragma unroll
        for (int ni = 0; ni < 8; ni++) {
            o[ni][0] *= al_lo; o[ni][1] *= al_lo;
            o[ni][2] *= al_hi; o[ni][3] *= al_hi;
        }

        // O += P @ V: P A-frags directly from s registers, LDSM interleaved
#pragma unroll
        for (int ks = 0; ks < 4; ks++) {
            uint32_t pf[4];
            pf[0] = pack_h2(s[2 * ks][0],     s[2 * ks][1]);
            pf[1] = pack_h2(s[2 * ks][2],     s[2 * ks][3]);
            pf[2] = pack_h2(s[2 * ks + 1][0], s[2 * ks + 1][1]);
            pf[3] = pack_h2(s[2 * ks + 1][2], s[2 * ks + 1][3]);
#pragma unroll
            for (int nj = 0; nj < 8; nj += 2) {
                uint32_t b00, b01, b10, b11;
                ldsm_x4(b00, b01, b10, b11,
                        vb_a[p] + (nj * 8) * 144 + ks * 32 + b_off);
                MMA_F16(o[nj],     pf, b00, b01);
                MMA_F16(o[nj + 1], pf, b10, b11);
            }
        }
    }

    // epilogue: normalize, write ctx as half
    const int b = bh >> 4;
    const int h = bh & 15;
    const float inv_lo = 1.f / l_lo;
    const float inv_hi = 1.f / l_hi;
#pragma unroll
    for (int ni = 0; ni < 8; ni++) {
        int d = ni * 8 + lt * 2;
        size_t i0 = (((size_t)b * Sq + row_lo) << 10) + h * HD + d;
        size_t i1 = (((size_t)b * Sq + row_hi) << 10) + h * HD + d;
        *(uint32_t*)&g_ctx[i0] = pack_h2(o[ni][0] * inv_lo, o[ni][1] * inv_lo);
        *(uint32_t*)&g_ctx[i1] = pack_h2(o[ni][2] * inv_hi, o[ni][3] * inv_hi);
    }
}

// ---------------------------------------------------------------------------
// Launch
// ---------------------------------------------------------------------------
extern "C" void kernel_launch(void* const* d_in, const int* in_sizes, int n_in,
                              void* d_out, int out_size)
{
    const float* X       = (const float*)d_in[0];
    const float* W_qkv   = (const float*)d_in[2];
    const float* b_qkv   = (const float*)d_in[3];
    const float* W_dense = (const float*)d_in[4];
    const float* b_dense = (const float*)d_in[5];
    float* out = (float*)d_out;

    (void)in_sizes; (void)n_in; (void)out_size;

    __half *p_Xh, *p_Wqt, *p_Wdt, *p_ctx;
    cudaGetSymbolAddress((void**)&p_Xh,  g_Xh);
    cudaGetSymbolAddress((void**)&p_Wqt, g_Wqt);
    cudaGetSymbolAddress((void**)&p_Wdt, g_Wdt);
    cudaGetSymbolAddress((void**)&p_ctx, g_ctx);

    cudaFuncSetAttribute(gemm_h<1>, cudaFuncAttributeMaxDynamicSharedMemorySize, G_SMEM);
    cudaFuncSetAttribute(gemm_h<0>, cudaFuncAttributeMaxDynamicSharedMemorySize, G_SMEM);
    cudaFuncSetAttribute(attn_h, cudaFuncAttributeMaxDynamicSharedMemorySize, AT_WORDS * 4);

    // 0. fused prep: X -> half; W_qkv, W_dense -> transposed half
    prep_all<<<NB_CONV + NB_TQ + NB_TD, 256>>>(
        (const float4*)X, (uint2*)p_Xh, W_qkv, p_Wqt, W_dense, p_Wdt);

    // 1. QKV projection -> g_q (0.125*log2e scaled), g_k, g_vT
    gemm_h<1><<<dim3(3 * Hd / 128, M1 / 128), 128, G_SMEM>>>(p_Xh, p_Wqt, b_qkv, nullptr, 3 * Hd);

    // 2. fp16 causal flash attention (log2-domain softmax) -> g_ctx (half)
    attn_h<<<dim3(16, BH), 256, AT_WORDS * 4>>>();

    // 3. output projection -> fp32 out
    gemm_h<0><<<dim3(Hd / 128, M1 / 128), 128, G_SMEM>>>(p_ctx, p_Wdt, b_dense, out, Hd);
}

// round 15
// speedup vs baseline: 2.6954x; 1.0140x over previous
#include <cuda_runtime.h>
#include <cuda_fp16.h>
#include <cstdint>

// Problem constants
#define Bsz 4
#define Sq  2048
#define Hd  1024
#define NH  16
#define HD  64
#define BH  (Bsz*NH)          // 64
#define M1  (Bsz*Sq)          // 8192
#define QKV_STRIDE ((size_t)BH*Sq*HD) // 8388608 halves per tensor

// Scratch (__device__ globals)
__device__ __half g_q  [QKV_STRIDE];            // [BH][S][HD], pre-scaled 0.125*log2e
__device__ __half g_k  [QKV_STRIDE];            // [BH][S][HD]
__device__ __half g_vT [QKV_STRIDE];            // [BH][HD][S]  (transposed)
__device__ __half g_ctx[(size_t)M1 * Hd];       // [B][S][H]
__device__ __half g_Xh [(size_t)M1 * Hd];       // X as half
__device__ __half g_Wqt[(size_t)3 * Hd * Hd];   // W_qkv^T  [3072][1024]
__device__ __half g_Wdt[(size_t)Hd * Hd];       // W_dense^T [1024][1024]

// ---------------------------------------------------------------------------
// Helpers
// ---------------------------------------------------------------------------
__device__ __forceinline__ uint32_t pack_h2(float a, float b) {
    __half2 h = __floats2half2_rn(a, b);
    return *(uint32_t*)&h;
}
__device__ __forceinline__ float ex2(float x) {
    float y;
    asm("ex2.approx.ftz.f32 %0, %1;" : "=f"(y) : "f"(x));
    return y;
}
__device__ __forceinline__ void cp_async16(void* smem_dst, const void* gmem_src) {
    uint32_t s = (uint32_t)__cvta_generic_to_shared(smem_dst);
    asm volatile("cp.async.cg.shared.global [%0], [%1], 16;\n" :: "r"(s), "l"(gmem_src));
}
#define CP_COMMIT() asm volatile("cp.async.commit_group;\n")
#define CP_WAIT(n)  asm volatile("cp.async.wait_group %0;\n" :: "n"(n))

__device__ __forceinline__ void ldsm_x4(uint32_t& r0, uint32_t& r1,
                                        uint32_t& r2, uint32_t& r3, uint32_t saddr) {
    asm volatile("ldmatrix.sync.aligned.m8n8.x4.shared.b16 {%0,%1,%2,%3}, [%4];"
                 : "=r"(r0), "=r"(r1), "=r"(r2), "=r"(r3) : "r"(saddr));
}

// fp16 mma, fp32 accum. A row-major (4 regs), B col-major (2 regs).
#define MMA_F16(acc, a, b0, b1)                                                \
    asm volatile(                                                              \
        "mma.sync.aligned.m16n8k16.row.col.f32.f16.f16.f32 "                   \
        "{%0,%1,%2,%3}, {%4,%5,%6,%7}, {%8,%9}, {%0,%1,%2,%3};\n"              \
        : "+f"((acc)[0]), "+f"((acc)[1]), "+f"((acc)[2]), "+f"((acc)[3])       \
        : "r"((a)[0]), "r"((a)[1]), "r"((a)[2]), "r"((a)[3]),                  \
          "r"(b0), "r"(b1))

// ---------------------------------------------------------------------------
// Fused prep (single launch):
//   blocks [0, NB_CONV)               : X fp32 -> half
//   blocks [NB_CONV, +NB_TQ)          : W_qkv  [1024][3072] -> W_qkv^T half
//   blocks [NB_CONV+NB_TQ, +NB_TD)    : W_dense[1024][1024] -> W_dense^T half
// ---------------------------------------------------------------------------
#define NB_CONV (M1 * Hd / 4 / 256)          // 8192
#define NB_TQ   ((3 * Hd / 32) * (Hd / 32))  // 3072
#define NB_TD   ((Hd / 32) * (Hd / 32))      // 1024

__global__ __launch_bounds__(256)
void prep_all(const float4* __restrict__ X4, uint2* __restrict__ Xh4,
              const float* __restrict__ Wq, __half* __restrict__ Wqt,
              const float* __restrict__ Wd, __half* __restrict__ Wdt)
{
    const int b = blockIdx.x;
    const int tid = threadIdx.x;

    if (b < NB_CONV) {
        int i = b * 256 + tid;
        float4 v = X4[i];
        Xh4[i] = make_uint2(pack_h2(v.x, v.y), pack_h2(v.z, v.w));
        return;
    }
    // transpose section: src[R][C] -> dst[C][R]
    __shared__ __half t[32][33];
    const float* src;  __half* dst;  int R, C, tb;
    if (b < NB_CONV + NB_TQ) { tb = b - NB_CONV;         src = Wq; dst = Wqt; R = Hd; C = 3 * Hd; }
    else                     { tb = b - NB_CONV - NB_TQ; src = Wd; dst = Wdt; R = Hd; C = Hd; }
    const int nbx = C / 32;
    const int c0 = (tb % nbx) * 32, r0 = (tb / nbx) * 32;
    const int tx = tid & 31, ty = tid >> 5;   // 32 x 8
#pragma unroll
    for (int i = 0; i < 32; i += 8)
        t[ty + i][tx] = __float2half_rn(src[(size_t)(r0 + ty + i) * C + c0 + tx]);
    __syncthreads();
#pragma unroll
    for (int i = 0; i < 32; i += 8)
        dst[(size_t)(c0 + ty + i) * R + r0 + tx] = t[tx][ty + i];
}

// ---------------------------------------------------------------------------
// FP16 GEMM: C[M,N] = A[M,1024] @ Bw^T + bias.
// Block tile 128 x BN, 4 warps, warp tile 64 x (BN/2). K-chunk 64,
// 2-stage cp.async ring, ONE sync per iter.
// BN=128: warps 2x2, warp tile 64x64, 3 CTAs/SM  (GEMM1)
// BN=64 : warps 2x2, warp tile 64x32, 4 CTAs/SM  (GEMM2 — kills wave tail)
// Smem rows 72 halves (144B stride; LDSM conflict-free).
// MODE 0: fp32 row-major C.  MODE 1: scatter to g_q(0.125*log2e)/g_k/g_vT.
// ---------------------------------------------------------------------------
#define QSCALE  (0.125f * 1.4426950408889634f)

template<int MODE, int BN>
__global__ __launch_bounds__(128, BN == 64 ? 4 : 3)
void gemm_h(const __half* __restrict__ A, const __half* __restrict__ Bw,
            const float* __restrict__ bias, float* __restrict__ C, int N)
{
    constexpr int STG_H = (128 + BN) * 72;   // halves per stage (A+B)
    constexpr int NWT   = BN / 16;           // n-subtiles (8-wide) per warp

    extern __shared__ __half gsm[];

    const int tid  = threadIdx.x;
    const int lane = tid & 31;
    const int warp = tid >> 5;
    const int wm   = (warp >> 1) * 64;
    const int wn   = (warp & 1) * (BN / 2);
    const int brow = blockIdx.y * 128;
    const int bcol = blockIdx.x * BN;
    const int lg = lane >> 2;
    const int lt = lane & 3;

    const uint32_t a_off = (uint32_t)((lane & 15) * 144 + (lane >> 4) * 16);
    const uint32_t b_off = (uint32_t)((((lane >> 4) * 8) + (lane & 7)) * 144
                                      + ((lane >> 3) & 1) * 16);

    const uint32_t sbase = (uint32_t)__cvta_generic_to_shared(gsm);

    auto fill = [&](int k0, int st) {
        __half* Abuf = gsm + st * STG_H;
        __half* Bbuf = Abuf + 128 * 72;
        const int r = tid >> 3, sg = tid & 7;
#pragma unroll
        for (int i = 0; i < 8; i++)              // A: 128 rows x 128B
            cp_async16(&Abuf[(r + i * 16) * 72 + sg * 8],
                       A + (size_t)(brow + r + i * 16) * 1024 + k0 + sg * 8);
#pragma unroll
        for (int i = 0; i < BN / 16; i++)        // B: BN rows x 128B
            cp_async16(&Bbuf[(r + i * 16) * 72 + sg * 8],
                       Bw + (size_t)(bcol + r + i * 16) * 1024 + k0 + sg * 8);
        CP_COMMIT();
    };

    float acc[4][NWT][4];
#pragma unroll
    for (int mi = 0; mi < 4; mi++)
#pragma unroll
        for (int ni = 0; ni < NWT; ni++)
#pragma unroll
            for (int r = 0; r < 4; r++) acc[mi][ni][r] = 0.f;

    const int NIT = 1024 / 64;   // 16
    fill(0, 0);

    for (int it = 0; it < NIT; ++it) {
        CP_WAIT(0);
        __syncthreads();
        if (it + 1 < NIT) fill((it + 1) * 64, (it + 1) & 1);

        const uint32_t aS = sbase + (it & 1) * STG_H * 2;
        const uint32_t bS = aS + 128 * 72 * 2;

#pragma unroll
        for (int ks = 0; ks < 4; ++ks) {
            uint32_t af[4][4];
#pragma unroll
            for (int mi = 0; mi < 4; mi++)
                ldsm_x4(af[mi][0], af[mi][1], af[mi][2], af[mi][3],
                        aS + (wm + mi * 16) * 144 + ks * 32 + a_off);
#pragma unroll
            for (int nj = 0; nj < NWT; nj += 2) {
                uint32_t b00, b01, b10, b11;
                ldsm_x4(b00, b01, b10, b11,
                        bS + (wn + nj * 8) * 144 + ks * 32 + b_off);
#pragma unroll
                for (int mi = 0; mi < 4; mi++) {
                    MMA_F16(acc[mi][nj],     af[mi], b00, b01);
                    MMA_F16(acc[mi][nj + 1], af[mi], b10, b11);
                }
            }
        }
    }

    // epilogue
#pragma unroll
    for (int mi = 0; mi < 4; mi++) {
#pragma unroll
        for (int ni = 0; ni < NWT; ni++) {
            int gr = brow + wm + mi * 16 + lg;
            int gc = bcol + wn + ni * 8 + lt * 2;
            float bx = bias[gc], by = bias[gc + 1];
            float2 v0 = make_float2(acc[mi][ni][0] + bx, acc[mi][ni][1] + by);
            float2 v1 = make_float2(acc[mi][ni][2] + bx, acc[mi][ni][3] + by);
            if (MODE == 0) {
                *(float2*)&C[(size_t)gr * N + gc]       = v0;
                *(float2*)&C[(size_t)(gr + 8) * N + gc] = v1;
            } else {
                int which = gc >> 10;
                int hh    = (gc >> 6) & 15;
                int d     = gc & 63;
#pragma unroll
                for (int rr = 0; rr < 2; rr++) {
                    int row = gr + rr * 8;
                    int b   = row >> 11;
                    int s   = row & 2047;
                    int bh  = b * NH + hh;
                    float2 v = rr ? v1 : v0;
                    if (which == 0) {
                        *(uint32_t*)&g_q[((size_t)bh * Sq + s) * HD + d] =
                            pack_h2(v.x * QSCALE, v.y * QSCALE);
                    } else if (which == 1) {
                        *(uint32_t*)&g_k[((size_t)bh * Sq + s) * HD + d] =
                            pack_h2(v.x, v.y);
                    } else {
                        g_vT[((size_t)bh * HD + d)     * Sq + s] = __float2half_rn(v.x);
                        g_vT[((size_t)bh * HD + d + 1) * Sq + s] = __float2half_rn(v.y);
                    }
                }
            }
        }
    }
}

#define G_SMEM1 (2 * (128 + 128) * 72 * 2)   // 73728 B  (BN=128)
#define G_SMEM0 (2 * (128 + 64) * 72 * 2)    // 55296 B  (BN=64)

// ---------------------------------------------------------------------------
// FP16 causal flash attention, log2-domain softmax (scale pre-folded into Q).
// BM=128 (8 warps x 16 rows), BN=64, HD=64, double-buffered K/V,
// sync every tile, P in registers. Rows 36 words (144B, LDSM conflict-free).
// ---------------------------------------------------------------------------
#define AQ_W (128 * 36)
#define AK_W (64 * 36)
#define AT_WORDS (AQ_W + 4 * AK_W)   // 13824 words = 55296 B

__global__ __launch_bounds__(256, 2)
void attn_h()
{
    extern __shared__ uint32_t sm[];
    uint32_t* Qs  = sm;
    uint32_t* Kb[2]  = { sm + AQ_W,            sm + AQ_W + 2 * AK_W };
    uint32_t* Vb[2]  = { sm + AQ_W + AK_W,     sm + AQ_W + 3 * AK_W };

    const int tid  = threadIdx.x;
    const int lane = tid & 31;
    const int warp = tid >> 5;
    const int lg = lane >> 2;
    const int lt = lane & 3;
    const int qt = 15 - blockIdx.x;     // heavy tiles first
    const int bh = blockIdx.y;
    const int q0 = qt * 128;
    const int wm = warp * 16;

    const uint32_t a_off = (uint32_t)((lane & 15) * 144 + (lane >> 4) * 16);
    const uint32_t b_off = (uint32_t)((((lane >> 4) * 8) + (lane & 7)) * 144
                                      + ((lane >> 3) & 1) * 16);

    const uint32_t qs_a = (uint32_t)__cvta_generic_to_shared(Qs);
    const uint32_t kb_a[2] = { (uint32_t)__cvta_generic_to_shared(Kb[0]),
                               (uint32_t)__cvta_generic_to_shared(Kb[1]) };
    const uint32_t vb_a[2] = { (uint32_t)__cvta_generic_to_shared(Vb[0]),
                               (uint32_t)__cvta_generic_to_shared(Vb[1]) };

    // Q load
    const __half* q_ptr = g_q + ((size_t)bh * Sq + q0) * HD;
#pragma unroll
    for (int i = 0; i < 4; i++) {
        int id = tid + i * 256;
        int row = id >> 3, seg = id & 7;
        cp_async16((char*)&Qs[row * 36] + seg * 16, q_ptr + (size_t)row * HD + seg * 8);
    }
    CP_COMMIT();

    auto load_kv = [&](int kt, int b) {
        const __half* k_ptr = g_k  + ((size_t)bh * Sq + kt * 64) * HD;
        const __half* v_ptr = g_vT + (size_t)bh * HD * Sq + kt * 64;
#pragma unroll
        for (int i = 0; i < 2; i++) {
            int id = tid + i * 256;
            int row = id >> 3, seg = id & 7;
            cp_async16((char*)&Kb[b][row * 36] + seg * 16, k_ptr + (size_t)row * HD + seg * 8);
            cp_async16((char*)&Vb[b][row * 36] + seg * 16, v_ptr + (size_t)row * Sq + seg * 8);
        }
        CP_COMMIT();
    };
    load_kv(0, 0);

    CP_WAIT(1);
    __syncthreads();

    // Q fragments via ldmatrix (warp-private rows)
    uint32_t qf[4][4];
#pragma unroll
    for (int ks = 0; ks < 4; ks++)
        ldsm_x4(qf[ks][0], qf[ks][1], qf[ks][2], qf[ks][3],
                qs_a + wm * 144 + ks * 32 + a_off);

    float m_lo = -1e30f, m_hi = -1e30f, l_lo = 0.f, l_hi = 0.f;
    float o[8][4];
#pragma unroll
    for (int ni = 0; ni < 8; ni++)
#pragma unroll
        for (int c = 0; c < 4; c++) o[ni][c] = 0.f;

    const int row_lo = q0 + wm + lg;
    const int row_hi = row_lo + 8;
    const int nkt = 2 * qt + 2;

    for (int kt = 0; kt < nkt; kt++) {
        const int p = kt & 1;
        CP_WAIT(0);
        __syncthreads();
        if (kt + 1 < nkt) load_kv(kt + 1, p ^ 1);

        // S = Q @ K^T (log2 domain; scale folded into Q)
        float s[8][4];
#pragma unroll
        for (int ni = 0; ni < 8; ni++)
#pragma unroll
            for (int c = 0; c < 4; c++) s[ni][c] = 0.f;

#pragma unroll
        for (int ks = 0; ks < 4; ks++) {
#pragma unroll
            for (int nj = 0; nj < 8; nj += 2) {
                uint32_t b00, b01, b10, b11;
                ldsm_x4(b00, b01, b10, b11,
                        kb_a[p] + (nj * 8) * 144 + ks * 32 + b_off);
                MMA_F16(s[nj],     qf[ks], b00, b01);
                MMA_F16(s[nj + 1], qf[ks], b10, b11);
            }
        }

        if (kt >= 2 * qt) {
            const int colb = kt * 64;
#pragma unroll
            for (int ni = 0; ni < 8; ni++) {
                int c0 = colb + ni * 8 + lt * 2;
                if (c0 > row_lo)     s[ni][0] = -1e30f;
                if (c0 + 1 > row_lo) s[ni][1] = -1e30f;
                if (c0 > row_hi)     s[ni][2] = -1e30f;
                if (c0 + 1 > row_hi) s[ni][3] = -1e30f;
            }
        }

        // online softmax in log2 domain (reg stats, quad reduce)
        float rx_lo = -1e30f, rx_hi = -1e30f;
#pragma unroll
        for (int ni = 0; ni < 8; ni++) {
            rx_lo = fmaxf(rx_lo, fmaxf(s[ni][0], s[ni][1]));
            rx_hi = fmaxf(rx_hi, fmaxf(s[ni][2], s[ni][3]));
        }
        rx_lo = fmaxf(rx_lo, __shfl_xor_sync(0xffffffffu, rx_lo, 1));
        rx_lo = fmaxf(rx_lo, __shfl_xor_sync(0xffffffffu, rx_lo, 2));
        rx_hi = fmaxf(rx_hi, __shfl_xor_sync(0xffffffffu, rx_hi, 1));
        rx_hi = fmaxf(rx_hi, __shfl_xor_sync(0xffffffffu, rx_hi, 2));

        float mn_lo = fmaxf(m_lo, rx_lo);
        float mn_hi = fmaxf(m_hi, rx_hi);
        float al_lo = ex2(m_lo - mn_lo);
        float al_hi = ex2(m_hi - mn_hi);
        m_lo = mn_lo; m_hi = mn_hi;

        float rs_lo = 0.f, rs_hi = 0.f;
#pragma unroll
        for (int ni = 0; ni < 8; ni++) {
            s[ni][0] = ex2(s[ni][0] - mn_lo);
            s[ni][1] = ex2(s[ni][1] - mn_lo);
            s[ni][2] = ex2(s[ni][2] - mn_hi);
            s[ni][3] = ex2(s[ni][3] - mn_hi);
            rs_lo += s[ni][0] + s[ni][1];
            rs_hi += s[ni][2] + s[ni][3];
        }
        rs_lo += __shfl_xor_sync(0xffffffffu, rs_lo, 1);
        rs_lo += __shfl_xor_sync(0xffffffffu, rs_lo, 2);
        rs_hi += __shfl_xor_sync(0xffffffffu, rs_hi, 1);
        rs_hi += __shfl_xor_sync(0xffffffffu, rs_hi, 2);
        l_lo = l_lo * al_lo + rs_lo;
        l_hi = l_hi * al_hi + rs_hi;

#pragma unroll
        for (int ni = 0; ni < 8; ni++) {
            o[ni][0] *= al_lo; o[ni][1] *= al_lo;
            o[ni][2] *= al_hi; o[ni][3] *= al_hi;
        }

        // O += P @ V: P A-frags directly from s registers, LDSM interleaved
#pragma unroll
        for (int ks = 0; ks < 4; ks++) {
            uint32_t pf[4];
            pf[0] = pack_h2(s[2 * ks][0],     s[2 * ks][1]);
            pf[1] = pack_h2(s[2 * ks][2],     s[2 * ks][3]);
            pf[2] = pack_h2(s[2 * ks + 1][0], s[2 * ks + 1][1]);
            pf[3] = pack_h2(s[2 * ks + 1][2], s[2 * ks + 1][3]);
#pragma unroll
            for (int nj = 0; nj < 8; nj += 2) {
                uint32_t b00, b01, b10, b11;
                ldsm_x4(b00, b01, b10, b11,
                        vb_a[p] + (nj * 8) * 144 + ks * 32 + b_off);
                MMA_F16(o[nj],     pf, b00, b01);
                MMA_F16(o[nj + 1], pf, b10, b11);
            }
        }
    }

    // epilogue: normalize, write ctx as half
    const int b = bh >> 4;
    const int h = bh & 15;
    const float inv_lo = 1.f / l_lo;
    const float inv_hi = 1.f / l_hi;
#pragma unroll
    for (int ni = 0; ni < 8; ni++) {
        int d = ni * 8 + lt * 2;
        size_t i0 = (((size_t)b * Sq + row_lo) << 10) + h * HD + d;
        size_t i1 = (((size_t)b * Sq + row_hi) << 10) + h * HD + d;
        *(uint32_t*)&g_ctx[i0] = pack_h2(o[ni][0] * inv_lo, o[ni][1] * inv_lo);
        *(uint32_t*)&g_ctx[i1] = pack_h2(o[ni][2] * inv_hi, o[ni][3] * inv_hi);
    }
}

// ---------------------------------------------------------------------------
// Launch
// ---------------------------------------------------------------------------
extern "C" void kernel_launch(void* const* d_in, const int* in_sizes, int n_in,
                              void* d_out, int out_size)
{
    const float* X       = (const float*)d_in[0];
    const float* W_qkv   = (const float*)d_in[2];
    const float* b_qkv   = (const float*)d_in[3];
    const float* W_dense = (const float*)d_in[4];
    const float* b_dense = (const float*)d_in[5];
    float* out = (float*)d_out;

    (void)in_sizes; (void)n_in; (void)out_size;

    __half *p_Xh, *p_Wqt, *p_Wdt, *p_ctx;
    cudaGetSymbolAddress((void**)&p_Xh,  g_Xh);
    cudaGetSymbolAddress((void**)&p_Wqt, g_Wqt);
    cudaGetSymbolAddress((void**)&p_Wdt, g_Wdt);
    cudaGetSymbolAddress((void**)&p_ctx, g_ctx);

    cudaFuncSetAttribute((const void*)gemm_h<1, 128>,
                         cudaFuncAttributeMaxDynamicSharedMemorySize, G_SMEM1);
    cudaFuncSetAttribute((const void*)gemm_h<0, 64>,
                         cudaFuncAttributeMaxDynamicSharedMemorySize, G_SMEM0);
    cudaFuncSetAttribute(attn_h, cudaFuncAttributeMaxDynamicSharedMemorySize, AT_WORDS * 4);

    // 0. fused prep: X -> half; W_qkv, W_dense -> transposed half
    prep_all<<<NB_CONV + NB_TQ + NB_TD, 256>>>(
        (const float4*)X, (uint2*)p_Xh, W_qkv, p_Wqt, W_dense, p_Wdt);

    // 1. QKV projection (128x128 tiles) -> g_q (0.125*log2e scaled), g_k, g_vT
    gemm_h<1, 128><<<dim3(3 * Hd / 128, M1 / 128), 128, G_SMEM1>>>(
        p_Xh, p_Wqt, b_qkv, nullptr, 3 * Hd);

    // 2. fp16 causal flash attention (log2-domain softmax) -> g_ctx (half)
    attn_h<<<dim3(16, BH), 256, AT_WORDS * 4>>>();

    // 3. output projection (128x64 tiles, occ 4 — wave-tail fix) -> fp32 out
    gemm_h<0, 64><<<dim3(Hd / 64, M1 / 128), 128, G_SMEM0>>>(
        p_ctx, p_Wdt, b_dense, out, Hd);
}

// round 17
// speedup vs baseline: 2.7082x; 1.0048x over previous
#include <cuda_runtime.h>
#include <cuda_fp16.h>
#include <cstdint>

// Problem constants
#define Bsz 4
#define Sq  2048
#define Hd  1024
#define NH  16
#define HD  64
#define BH  (Bsz*NH)          // 64
#define M1  (Bsz*Sq)          // 8192
#define QKV_STRIDE ((size_t)BH*Sq*HD) // 8388608 halves per tensor

// Scratch (__device__ globals)
__device__ __half g_q  [QKV_STRIDE];            // [BH][S][HD], pre-scaled 0.125*log2e
__device__ __half g_k  [QKV_STRIDE];            // [BH][S][HD]
__device__ __half g_vT [QKV_STRIDE];            // [BH][HD][S]  (transposed)
__device__ __half g_ctx[(size_t)M1 * Hd];       // [B][S][H]
__device__ __half g_Xh [(size_t)M1 * Hd];       // X as half
__device__ __half g_Wqt[(size_t)3 * Hd * Hd];   // W_qkv^T  [3072][1024]
__device__ __half g_Wdt[(size_t)Hd * Hd];       // W_dense^T [1024][1024]

// ---------------------------------------------------------------------------
// Helpers
// ---------------------------------------------------------------------------
__device__ __forceinline__ uint32_t pack_h2(float a, float b) {
    __half2 h = __floats2half2_rn(a, b);
    return *(uint32_t*)&h;
}
__device__ __forceinline__ float ex2(float x) {
    float y;
    asm("ex2.approx.ftz.f32 %0, %1;" : "=f"(y) : "f"(x));
    return y;
}
__device__ __forceinline__ uint32_t ex2_h2(uint32_t x) {
    uint32_t y;
    asm("ex2.approx.f16x2 %0, %1;" : "=r"(y) : "r"(x));
    return y;
}
__device__ __forceinline__ void cp_async16(void* smem_dst, const void* gmem_src) {
    uint32_t s = (uint32_t)__cvta_generic_to_shared(smem_dst);
    asm volatile("cp.async.cg.shared.global [%0], [%1], 16;\n" :: "r"(s), "l"(gmem_src));
}
#define CP_COMMIT() asm volatile("cp.async.commit_group;\n")
#define CP_WAIT(n)  asm volatile("cp.async.wait_group %0;\n" :: "n"(n))

__device__ __forceinline__ void ldsm_x4(uint32_t& r0, uint32_t& r1,
                                        uint32_t& r2, uint32_t& r3, uint32_t saddr) {
    asm volatile("ldmatrix.sync.aligned.m8n8.x4.shared.b16 {%0,%1,%2,%3}, [%4];"
                 : "=r"(r0), "=r"(r1), "=r"(r2), "=r"(r3) : "r"(saddr));
}

// fp16 mma, fp32 accum. A row-major (4 regs), B col-major (2 regs).
#define MMA_F16(acc, a, b0, b1)                                                \
    asm volatile(                                                              \
        "mma.sync.aligned.m16n8k16.row.col.f32.f16.f16.f32 "                   \
        "{%0,%1,%2,%3}, {%4,%5,%6,%7}, {%8,%9}, {%0,%1,%2,%3};\n"              \
        : "+f"((acc)[0]), "+f"((acc)[1]), "+f"((acc)[2]), "+f"((acc)[3])       \
        : "r"((a)[0]), "r"((a)[1]), "r"((a)[2]), "r"((a)[3]),                  \
          "r"(b0), "r"(b1))

// ---------------------------------------------------------------------------
// Fused prep (single launch):
//   blocks [0, NB_CONV)               : X fp32 -> half
//   blocks [NB_CONV, +NB_TQ)          : W_qkv  [1024][3072] -> W_qkv^T half
//   blocks [NB_CONV+NB_TQ, +NB_TD)    : W_dense[1024][1024] -> W_dense^T half
// ---------------------------------------------------------------------------
#define NB_CONV (M1 * Hd / 4 / 256)          // 8192
#define NB_TQ   ((3 * Hd / 32) * (Hd / 32))  // 3072
#define NB_TD   ((Hd / 32) * (Hd / 32))      // 1024

__global__ __launch_bounds__(256)
void prep_all(const float4* __restrict__ X4, uint2* __restrict__ Xh4,
              const float* __restrict__ Wq, __half* __restrict__ Wqt,
              const float* __restrict__ Wd, __half* __restrict__ Wdt)
{
    const int b = blockIdx.x;
    const int tid = threadIdx.x;

    if (b < NB_CONV) {
        int i = b * 256 + tid;
        float4 v = X4[i];
        Xh4[i] = make_uint2(pack_h2(v.x, v.y), pack_h2(v.z, v.w));
        return;
    }
    // transpose section: src[R][C] -> dst[C][R]
    __shared__ __half t[32][33];
    const float* src;  __half* dst;  int R, C, tb;
    if (b < NB_CONV + NB_TQ) { tb = b - NB_CONV;         src = Wq; dst = Wqt; R = Hd; C = 3 * Hd; }
    else                     { tb = b - NB_CONV - NB_TQ; src = Wd; dst = Wdt; R = Hd; C = Hd; }
    const int nbx = C / 32;
    const int c0 = (tb % nbx) * 32, r0 = (tb / nbx) * 32;
    const int tx = tid & 31, ty = tid >> 5;   // 32 x 8
#pragma unroll
    for (int i = 0; i < 32; i += 8)
        t[ty + i][tx] = __float2half_rn(src[(size_t)(r0 + ty + i) * C + c0 + tx]);
    __syncthreads();
#pragma unroll
    for (int i = 0; i < 32; i += 8)
        dst[(size_t)(c0 + ty + i) * R + r0 + tx] = t[tx][ty + i];
}

// ---------------------------------------------------------------------------
// FP16 GEMM: C[M,N] = A[M,1024] @ Bw^T + bias.
// Block tile 128 x BN, 4 warps, warp tile 64 x (BN/2). K-chunk 64,
// 2-stage cp.async ring, ONE sync per iter.
// BN=128: 3 CTAs/SM (GEMM1).  BN=64: 4 CTAs/SM (GEMM2 — wave-tail fix).
// Smem rows 72 halves (144B stride; LDSM conflict-free).
// MODE 0: fp32 row-major C.  MODE 1: scatter to g_q(0.125*log2e)/g_k/g_vT.
// ---------------------------------------------------------------------------
#define QSCALE  (0.125f * 1.4426950408889634f)

template<int MODE, int BN>
__global__ __launch_bounds__(128, BN == 64 ? 4 : 3)
void gemm_h(const __half* __restrict__ A, const __half* __restrict__ Bw,
            const float* __restrict__ bias, float* __restrict__ C, int N)
{
    constexpr int STG_H = (128 + BN) * 72;   // halves per stage (A+B)
    constexpr int NWT   = BN / 16;           // n-subtiles (8-wide) per warp

    extern __shared__ __half gsm[];

    const int tid  = threadIdx.x;
    const int lane = tid & 31;
    const int warp = tid >> 5;
    const int wm   = (warp >> 1) * 64;
    const int wn   = (warp & 1) * (BN / 2);
    const int brow = blockIdx.y * 128;
    const int bcol = blockIdx.x * BN;
    const int lg = lane >> 2;
    const int lt = lane & 3;

    const uint32_t a_off = (uint32_t)((lane & 15) * 144 + (lane >> 4) * 16);
    const uint32_t b_off = (uint32_t)((((lane >> 4) * 8) + (lane & 7)) * 144
                                      + ((lane >> 3) & 1) * 16);

    const uint32_t sbase = (uint32_t)__cvta_generic_to_shared(gsm);

    auto fill = [&](int k0, int st) {
        __half* Abuf = gsm + st * STG_H;
        __half* Bbuf = Abuf + 128 * 72;
        const int r = tid >> 3, sg = tid & 7;
#pragma unroll
        for (int i = 0; i < 8; i++)              // A: 128 rows x 128B
            cp_async16(&Abuf[(r + i * 16) * 72 + sg * 8],
                       A + (size_t)(brow + r + i * 16) * 1024 + k0 + sg * 8);
#pragma unroll
        for (int i = 0; i < BN / 16; i++)        // B: BN rows x 128B
            cp_async16(&Bbuf[(r + i * 16) * 72 + sg * 8],
                       Bw + (size_t)(bcol + r + i * 16) * 1024 + k0 + sg * 8);
        CP_COMMIT();
    };

    float acc[4][NWT][4];
#pragma unroll
    for (int mi = 0; mi < 4; mi++)
#pragma unroll
        for (int ni = 0; ni < NWT; ni++)
#pragma unroll
            for (int r = 0; r < 4; r++) acc[mi][ni][r] = 0.f;

    const int NIT = 1024 / 64;   // 16
    fill(0, 0);

    for (int it = 0; it < NIT; ++it) {
        CP_WAIT(0);
        __syncthreads();
        if (it + 1 < NIT) fill((it + 1) * 64, (it + 1) & 1);

        const uint32_t aS = sbase + (it & 1) * STG_H * 2;
        const uint32_t bS = aS + 128 * 72 * 2;

#pragma unroll
        for (int ks = 0; ks < 4; ++ks) {
            uint32_t af[4][4];
#pragma unroll
            for (int mi = 0; mi < 4; mi++)
                ldsm_x4(af[mi][0], af[mi][1], af[mi][2], af[mi][3],
                        aS + (wm + mi * 16) * 144 + ks * 32 + a_off);
#pragma unroll
            for (int nj = 0; nj < NWT; nj += 2) {
                uint32_t b00, b01, b10, b11;
                ldsm_x4(b00, b01, b10, b11,
                        bS + (wn + nj * 8) * 144 + ks * 32 + b_off);
#pragma unroll
                for (int mi = 0; mi < 4; mi++) {
                    MMA_F16(acc[mi][nj],     af[mi], b00, b01);
                    MMA_F16(acc[mi][nj + 1], af[mi], b10, b11);
                }
            }
        }
    }

    // epilogue
#pragma unroll
    for (int mi = 0; mi < 4; mi++) {
#pragma unroll
        for (int ni = 0; ni < NWT; ni++) {
            int gr = brow + wm + mi * 16 + lg;
            int gc = bcol + wn + ni * 8 + lt * 2;
            float bx = bias[gc], by = bias[gc + 1];
            float2 v0 = make_float2(acc[mi][ni][0] + bx, acc[mi][ni][1] + by);
            float2 v1 = make_float2(acc[mi][ni][2] + bx, acc[mi][ni][3] + by);
            if (MODE == 0) {
                *(float2*)&C[(size_t)gr * N + gc]       = v0;
                *(float2*)&C[(size_t)(gr + 8) * N + gc] = v1;
            } else {
                int which = gc >> 10;
                int hh    = (gc >> 6) & 15;
                int d     = gc & 63;
#pragma unroll
                for (int rr = 0; rr < 2; rr++) {
                    int row = gr + rr * 8;
                    int b   = row >> 11;
                    int s   = row & 2047;
                    int bh  = b * NH + hh;
                    float2 v = rr ? v1 : v0;
                    if (which == 0) {
                        *(uint32_t*)&g_q[((size_t)bh * Sq + s) * HD + d] =
                            pack_h2(v.x * QSCALE, v.y * QSCALE);
                    } else if (which == 1) {
                        *(uint32_t*)&g_k[((size_t)bh * Sq + s) * HD + d] =
                            pack_h2(v.x, v.y);
                    } else {
                        g_vT[((size_t)bh * HD + d)     * Sq + s] = __float2half_rn(v.x);
                        g_vT[((size_t)bh * HD + d + 1) * Sq + s] = __float2half_rn(v.y);
                    }
                }
            }
        }
    }
}

#define G_SMEM1 (2 * (128 + 128) * 72 * 2)   // 73728 B  (BN=128)
#define G_SMEM0 (2 * (128 + 64) * 72 * 2)    // 55296 B  (BN=64)

// ---------------------------------------------------------------------------
// FP16 causal flash attention, log2-domain softmax (scale pre-folded into Q).
// BM=128 (8 warps x 16 rows), BN=64, HD=64, double-buffered K/V,
// sync every tile, P in registers. Rows 36 words (144B, LDSM conflict-free).
// exp via ex2.approx.f16x2 on packed P-fragments (half the MUFU ops);
// row sums l via ones-B MMA (exactly consistent with fp16 P used in PV).
// Mask constant -3e4 keeps fp16 intermediates finite (exp underflows to 0).
// ---------------------------------------------------------------------------
#define AQ_W (128 * 36)
#define AK_W (64 * 36)
#define AT_WORDS (AQ_W + 4 * AK_W)   // 13824 words = 55296 B
#define MASK_NEG (-30000.0f)

__global__ __launch_bounds__(256, 2)
void attn_h()
{
    extern __shared__ uint32_t sm[];
    uint32_t* Qs  = sm;
    uint32_t* Kb[2]  = { sm + AQ_W,            sm + AQ_W + 2 * AK_W };
    uint32_t* Vb[2]  = { sm + AQ_W + AK_W,     sm + AQ_W + 3 * AK_W };

    const int tid  = threadIdx.x;
    const int lane = tid & 31;
    const int warp = tid >> 5;
    const int lg = lane >> 2;
    const int lt = lane & 3;
    const int qt = 15 - blockIdx.x;     // heavy tiles first
    const int bh = blockIdx.y;
    const int q0 = qt * 128;
    const int wm = warp * 16;

    const uint32_t a_off = (uint32_t)((lane & 15) * 144 + (lane >> 4) * 16);
    const uint32_t b_off = (uint32_t)((((lane >> 4) * 8) + (lane & 7)) * 144
                                      + ((lane >> 3) & 1) * 16);

    const uint32_t qs_a = (uint32_t)__cvta_generic_to_shared(Qs);
    const uint32_t kb_a[2] = { (uint32_t)__cvta_generic_to_shared(Kb[0]),
                               (uint32_t)__cvta_generic_to_shared(Kb[1]) };
    const uint32_t vb_a[2] = { (uint32_t)__cvta_generic_to_shared(Vb[0]),
                               (uint32_t)__cvta_generic_to_shared(Vb[1]) };

    const uint32_t ONES2 = pack_h2(1.0f, 1.0f);

    // Q load
    const __half* q_ptr = g_q + ((size_t)bh * Sq + q0) * HD;
#pragma unroll
    for (int i = 0; i < 4; i++) {
        int id = tid + i * 256;
        int row = id >> 3, seg = id & 7;
        cp_async16((char*)&Qs[row * 36] + seg * 16, q_ptr + (size_t)row * HD + seg * 8);
    }
    CP_COMMIT();

    auto load_kv = [&](int kt, int b) {
        const __half* k_ptr = g_k  + ((size_t)bh * Sq + kt * 64) * HD;
        const __half* v_ptr = g_vT + (size_t)bh * HD * Sq + kt * 64;
#pragma unroll
        for (int i = 0; i < 2; i++) {
            int id = tid + i * 256;
            int row = id >> 3, seg = id & 7;
            cp_async16((char*)&Kb[b][row * 36] + seg * 16, k_ptr + (size_t)row * HD + seg * 8);
            cp_async16((char*)&Vb[b][row * 36] + seg * 16, v_ptr + (size_t)row * Sq + seg * 8);
        }
        CP_COMMIT();
    };
    load_kv(0, 0);

    CP_WAIT(1);
    __syncthreads();

    // Q fragments via ldmatrix (warp-private rows)
    uint32_t qf[4][4];
#pragma unroll
    for (int ks = 0; ks < 4; ks++)
        ldsm_x4(qf[ks][0], qf[ks][1], qf[ks][2], qf[ks][3],
                qs_a + wm * 144 + ks * 32 + a_off);

    float m_lo = -1e30f, m_hi = -1e30f, l_lo = 0.f, l_hi = 0.f;
    float o[8][4];
#pragma unroll
    for (int ni = 0; ni < 8; ni++)
#pragma unroll
        for (int c = 0; c < 4; c++) o[ni][c] = 0.f;

    const int row_lo = q0 + wm + lg;
    const int row_hi = row_lo + 8;
    const int nkt = 2 * qt + 2;

    for (int kt = 0; kt < nkt; kt++) {
        const int p = kt & 1;
        CP_WAIT(0);
        __syncthreads();
        if (kt + 1 < nkt) load_kv(kt + 1, p ^ 1);

        // S = Q @ K^T (log2 domain; scale folded into Q)
        float s[8][4];
#pragma unroll
        for (int ni = 0; ni < 8; ni++)
#pragma unroll
            for (int c = 0; c < 4; c++) s[ni][c] = 0.f;

#pragma unroll
        for (int ks = 0; ks < 4; ks++) {
#pragma unroll
            for (int nj = 0; nj < 8; nj += 2) {
                uint32_t b00, b01, b10, b11;
                ldsm_x4(b00, b01, b10, b11,
                        kb_a[p] + (nj * 8) * 144 + ks * 32 + b_off);
                MMA_F16(s[nj],     qf[ks], b00, b01);
                MMA_F16(s[nj + 1], qf[ks], b10, b11);
            }
        }

        if (kt >= 2 * qt) {
            const int colb = kt * 64;
#pragma unroll
            for (int ni = 0; ni < 8; ni++) {
                int c0 = colb + ni * 8 + lt * 2;
                if (c0 > row_lo)     s[ni][0] = MASK_NEG;
                if (c0 + 1 > row_lo) s[ni][1] = MASK_NEG;
                if (c0 > row_hi)     s[ni][2] = MASK_NEG;
                if (c0 + 1 > row_hi) s[ni][3] = MASK_NEG;
            }
        }

        // running max (reg stats, quad reduce)
        float rx_lo = -1e30f, rx_hi = -1e30f;
#pragma unroll
        for (int ni = 0; ni < 8; ni++) {
            rx_lo = fmaxf(rx_lo, fmaxf(s[ni][0], s[ni][1]));
            rx_hi = fmaxf(rx_hi, fmaxf(s[ni][2], s[ni][3]));
        }
        rx_lo = fmaxf(rx_lo, __shfl_xor_sync(0xffffffffu, rx_lo, 1));
        rx_lo = fmaxf(rx_lo, __shfl_xor_sync(0xffffffffu, rx_lo, 2));
        rx_hi = fmaxf(rx_hi, __shfl_xor_sync(0xffffffffu, rx_hi, 1));
        rx_hi = fmaxf(rx_hi, __shfl_xor_sync(0xffffffffu, rx_hi, 2));

        float mn_lo = fmaxf(m_lo, rx_lo);
        float mn_hi = fmaxf(m_hi, rx_hi);
        float al_lo = ex2(m_lo - mn_lo);
        float al_hi = ex2(m_hi - mn_hi);
        m_lo = mn_lo; m_hi = mn_hi;

        // P = 2^(s - mn) via f16x2 exp on the packed fragments.
        uint32_t e_lo[8], e_hi[8];
#pragma unroll
        for (int ni = 0; ni < 8; ni++) {
            e_lo[ni] = ex2_h2(pack_h2(s[ni][0] - mn_lo, s[ni][1] - mn_lo));
            e_hi[ni] = ex2_h2(pack_h2(s[ni][2] - mn_hi, s[ni][3] - mn_hi));
        }

#pragma unroll
        for (int ni = 0; ni < 8; ni++) {
            o[ni][0] *= al_lo; o[ni][1] *= al_lo;
            o[ni][2] *= al_hi; o[ni][3] *= al_hi;
        }

        // O += P @ V; row sums of P via ones-B MMA (ls[0]=row lo, ls[2]=row hi)
        float ls[4] = {0.f, 0.f, 0.f, 0.f};
#pragma unroll
        for (int ks = 0; ks < 4; ks++) {
            uint32_t pf[4];
            pf[0] = e_lo[2 * ks];
            pf[1] = e_hi[2 * ks];
            pf[2] = e_lo[2 * ks + 1];
            pf[3] = e_hi[2 * ks + 1];
            MMA_F16(ls, pf, ONES2, ONES2);
#pragma unroll
            for (int nj = 0; nj < 8; nj += 2) {
                uint32_t b00, b01, b10, b11;
                ldsm_x4(b00, b01, b10, b11,
                        vb_a[p] + (nj * 8) * 144 + ks * 32 + b_off);
                MMA_F16(o[nj],     pf, b00, b01);
                MMA_F16(o[nj + 1], pf, b10, b11);
            }
        }
        l_lo = l_lo * al_lo + ls[0];
        l_hi = l_hi * al_hi + ls[2];
    }

    // epilogue: normalize, write ctx as half
    const int b = bh >> 4;
    const int h = bh & 15;
    const float inv_lo = 1.f / l_lo;
    const float inv_hi = 1.f / l_hi;
#pragma unroll
    for (int ni = 0; ni < 8; ni++) {
        int d = ni * 8 + lt * 2;
        size_t i0 = (((size_t)b * Sq + row_lo) << 10) + h * HD + d;
        size_t i1 = (((size_t)b * Sq + row_hi) << 10) + h * HD + d;
        *(uint32_t*)&g_ctx[i0] = pack_h2(o[ni][0] * inv_lo, o[ni][1] * inv_lo);
        *(uint32_t*)&g_ctx[i1] = pack_h2(o[ni][2] * inv_hi, o[ni][3] * inv_hi);
    }
}

// ---------------------------------------------------------------------------
// Launch
// ---------------------------------------------------------------------------
extern "C" void kernel_launch(void* const* d_in, const int* in_sizes, int n_in,
                              void* d_out, int out_size)
{
    const float* X       = (const float*)d_in[0];
    const float* W_qkv   = (const float*)d_in[2];
    const float* b_qkv   = (const float*)d_in[3];
    const float* W_dense = (const float*)d_in[4];
    const float* b_dense = (const float*)d_in[5];
    float* out = (float*)d_out;

    (void)in_sizes; (void)n_in; (void)out_size;

    __half *p_Xh, *p_Wqt, *p_Wdt, *p_ctx;
    cudaGetSymbolAddress((void**)&p_Xh,  g_Xh);
    cudaGetSymbolAddress((void**)&p_Wqt, g_Wqt);
    cudaGetSymbolAddress((void**)&p_Wdt, g_Wdt);
    cudaGetSymbolAddress((void**)&p_ctx, g_ctx);

    cudaFuncSetAttribute((const void*)gemm_h<1, 128>,
                         cudaFuncAttributeMaxDynamicSharedMemorySize, G_SMEM1);
    cudaFuncSetAttribute((const void*)gemm_h<0, 64>,
                         cudaFuncAttributeMaxDynamicSharedMemorySize, G_SMEM0);
    cudaFuncSetAttribute(attn_h, cudaFuncAttributeMaxDynamicSharedMemorySize, AT_WORDS * 4);

    // 0. fused prep: X -> half; W_qkv, W_dense -> transposed half
    prep_all<<<NB_CONV + NB_TQ + NB_TD, 256>>>(
        (const float4*)X, (uint2*)p_Xh, W_qkv, p_Wqt, W_dense, p_Wdt);

    // 1. QKV projection (128x128 tiles) -> g_q (0.125*log2e scaled), g_k, g_vT
    gemm_h<1, 128><<<dim3(3 * Hd / 128, M1 / 128), 128, G_SMEM1>>>(
        p_Xh, p_Wqt, b_qkv, nullptr, 3 * Hd);

    // 2. fp16 causal flash attention (f16x2 exp + ones-MMA row sums) -> g_ctx
    attn_h<<<dim3(16, BH), 256, AT_WORDS * 4>>>();

    // 3. output projection (128x64 tiles, occ 4) -> fp32 out
    gemm_h<0, 64><<<dim3(Hd / 64, M1 / 128), 128, G_SMEM0>>>(
        p_ctx, p_Wdt, b_dense, out, Hd);
}